// round 5
// baseline (speedup 1.0000x reference)
#include <cuda_runtime.h>
#include <cuda_bf16.h>
#include <math.h>
#include <stdint.h>

#define HID 2048
#define TOK 4096
#define NH 16
#define HD 128
#define SEQ 2048
#define QBF 127.0f

__device__ __nv_bfloat16 g_w8[4][HID * HID];
__device__ float g_s[4];
__device__ float g_part[4 * 64];
__device__ __nv_bfloat16 g_x8[TOK * HID];
__device__ float g_xg[TOK];
__device__ float g_q[TOK * HID];
__device__ float g_k[TOK * HID];
__device__ float g_v[TOK * HID];
__device__ float g_qr[TOK * HID];
__device__ float g_kr[TOK * HID];
__device__ float g_ctx[TOK * HID];
__device__ __nv_bfloat16 g_c8[TOK * HID];
__device__ float g_cg[TOK];
__device__ float g_tc[SEQ * 64];
__device__ float g_ts[SEQ * 64];

__device__ __forceinline__ uint32_t sptr(const void* p) {
    return (uint32_t)__cvta_generic_to_shared(p);
}

#define CP16(s, g) asm volatile("cp.async.ca.shared.global [%0], [%1], 16;\n" ::"r"(s), "l"(g))
#define CPC asm volatile("cp.async.commit_group;\n")
#define CPW(n) asm volatile("cp.async.wait_group %0;\n" ::"n"(n))
#define LDSM4(r0, r1, r2, r3, a)                                                        \
    asm volatile("ldmatrix.sync.aligned.m8n8.x4.shared.b16 {%0,%1,%2,%3}, [%4];\n"      \
                 : "=r"(r0), "=r"(r1), "=r"(r2), "=r"(r3) : "r"(a))
#define MMAB(d, a, b)                                                                   \
    asm volatile("mma.sync.aligned.m16n8k16.row.col.f32.bf16.bf16.f32 "                 \
                 "{%0,%1,%2,%3},{%4,%5,%6,%7},{%8,%9},{%0,%1,%2,%3};\n"                 \
                 : "+f"(d[0]), "+f"(d[1]), "+f"(d[2]), "+f"(d[3])                       \
                 : "r"(a[0]), "r"(a[1]), "r"(a[2]), "r"(a[3]), "r"(b[0]), "r"(b[1]))

// rope table: exact trig of the reference's fp32-rounded angle
__global__ __launch_bounds__(512) void k_tab() {
    int i = blockIdx.x * 512 + threadIdx.x;
    int s = i >> 6, dp = i & 63;
    float ff = (float)pow(10000.0, -(double)dp / 64.0);
    float angf = (float)s * ff;
    double ang = fmod((double)angf, 6.283185307179586476925287);
    g_tc[i] = (float)cos(ang);
    g_ts[i] = (float)sin(ang);
}

__global__ __launch_bounds__(256) void k_wabs_partial(const float* __restrict__ w0,
        const float* __restrict__ w1, const float* __restrict__ w2, const float* __restrict__ w3) {
    const float* w = (blockIdx.y == 0) ? w0 : (blockIdx.y == 1) ? w1 : (blockIdx.y == 2) ? w2 : w3;
    const float4* w4 = (const float4*)(w + (size_t)blockIdx.x * 65536);
    float s = 0.f;
    for (int i = threadIdx.x; i < 16384; i += 256) {
        float4 v = w4[i];
        s += fabsf(v.x) + fabsf(v.y) + fabsf(v.z) + fabsf(v.w);
    }
    __shared__ float red[256];
    red[threadIdx.x] = s;
    __syncthreads();
    for (int st = 128; st > 0; st >>= 1) {
        if (threadIdx.x < st) red[threadIdx.x] += red[threadIdx.x + st];
        __syncthreads();
    }
    if (threadIdx.x == 0) g_part[blockIdx.y * 64 + blockIdx.x] = red[0];
}

__global__ __launch_bounds__(64) void k_wabs_final() {
    __shared__ float red[64];
    red[threadIdx.x] = g_part[blockIdx.x * 64 + threadIdx.x];
    __syncthreads();
    for (int st = 32; st > 0; st >>= 1) {
        if (threadIdx.x < st) red[threadIdx.x] += red[threadIdx.x + st];
        __syncthreads();
    }
    if (threadIdx.x == 0) g_s[blockIdx.x] = red[0] / (float)(HID * HID) + 1e-5f;
}

__global__ __launch_bounds__(256) void k_quant_w(const float* __restrict__ w0,
        const float* __restrict__ w1, const float* __restrict__ w2, const float* __restrict__ w3) {
    int m = blockIdx.y;
    const float* w = (m == 0) ? w0 : (m == 1) ? w1 : (m == 2) ? w2 : w3;
    float s = g_s[m];
    int idx = (blockIdx.x * 256 + threadIdx.x) * 4;
    float4 v = *(const float4*)(w + idx);
    float qx = fminf(1.f, fmaxf(-1.f, rintf(v.x / s)));
    float qy = fminf(1.f, fmaxf(-1.f, rintf(v.y / s)));
    float qz = fminf(1.f, fmaxf(-1.f, rintf(v.z / s)));
    float qw = fminf(1.f, fmaxf(-1.f, rintf(v.w / s)));
    __nv_bfloat162 lo = __floats2bfloat162_rn(qx, qy);
    __nv_bfloat162 hi = __floats2bfloat162_rn(qz, qw);
    uint2 pk;
    pk.x = *(unsigned int*)&lo;
    pk.y = *(unsigned int*)&hi;
    *(uint2*)&g_w8[m][idx] = pk;
}

__global__ __launch_bounds__(256) void k_quant_act(const float* __restrict__ ext, int use_ctx) {
    int row = blockIdx.x;
    const float* src = use_ctx ? g_ctx : ext;
    __nv_bfloat16* dst = use_ctx ? g_c8 : g_x8;
    float* gout = use_ctx ? g_cg : g_xg;
    const float4* xr = (const float4*)(src + (size_t)row * HID);
    float4 v0 = xr[threadIdx.x];
    float4 v1 = xr[threadIdx.x + 256];
    float mx = fmaxf(fmaxf(fabsf(v0.x), fabsf(v0.y)), fmaxf(fabsf(v0.z), fabsf(v0.w)));
    mx = fmaxf(mx, fmaxf(fmaxf(fabsf(v1.x), fabsf(v1.y)), fmaxf(fabsf(v1.z), fabsf(v1.w))));
    __shared__ float red[256];
    red[threadIdx.x] = mx;
    __syncthreads();
    for (int st = 128; st > 0; st >>= 1) {
        if (threadIdx.x < st) red[threadIdx.x] = fmaxf(red[threadIdx.x], red[threadIdx.x + st]);
        __syncthreads();
    }
    float g = red[0] + 1e-5f;
    if (threadIdx.x == 0) gout[row] = g;
    float t = QBF / g;
    __nv_bfloat16* orow = dst + (size_t)row * HID;
    float4 vv[2] = {v0, v1};
    int offs[2] = {(int)threadIdx.x * 4, ((int)threadIdx.x + 256) * 4};
#pragma unroll
    for (int hh = 0; hh < 2; ++hh) {
        float a = fminf(QBF, fmaxf(-QBF, rintf(vv[hh].x * t)));
        float b = fminf(QBF, fmaxf(-QBF, rintf(vv[hh].y * t)));
        float c = fminf(QBF, fmaxf(-QBF, rintf(vv[hh].z * t)));
        float d = fminf(QBF, fmaxf(-QBF, rintf(vv[hh].w * t)));
        __nv_bfloat162 lo = __floats2bfloat162_rn(a, b);
        __nv_bfloat162 hi = __floats2bfloat162_rn(c, d);
        uint2 pk;
        pk.x = *(unsigned int*)&lo;
        pk.y = *(unsigned int*)&hi;
        *(uint2*)&orow[offs[hh]] = pk;
    }
}

__global__ __launch_bounds__(256) void k_gemm(int mat, float* __restrict__ dout) {
    __shared__ __nv_bfloat16 As[2][128 * 40];
    __shared__ __nv_bfloat16 Bs[2][128 * 40];
    const __nv_bfloat16* A = (mat == 3) ? g_c8 : g_x8;
    const float* gv = (mat == 3) ? g_cg : g_xg;
    const __nv_bfloat16* W = g_w8[mat];
    float* C = (mat == 0) ? g_q : (mat == 1) ? g_k : (mat == 2) ? g_v : dout;
    int tid = threadIdx.x;
    int bm = blockIdx.y * 128, bn = blockIdx.x * 128;
    int warp = tid >> 5, lane = tid & 31;
    int wm = (warp >> 2) * 64, wn = (warp & 3) * 32;
    float acc[4][4][4];
#pragma unroll
    for (int i = 0; i < 4; i++)
#pragma unroll
        for (int j = 0; j < 4; j++)
#pragma unroll
            for (int r = 0; r < 4; r++) acc[i][j][r] = 0.f;
    const __nv_bfloat16* Ab = A + (size_t)bm * HID;
    const __nv_bfloat16* Wb = W + (size_t)bn * HID;
#define GLOAD(bf, k0)                                                              \
    for (int c = tid; c < 512; c += 256) {                                         \
        int rr = c >> 2, kc = (c & 3) << 3;                                        \
        CP16(sptr(&As[bf][rr * 40 + kc]), Ab + (size_t)rr * HID + (k0) + kc);      \
        CP16(sptr(&Bs[bf][rr * 40 + kc]), Wb + (size_t)rr * HID + (k0) + kc);      \
    }
    GLOAD(0, 0);
    CPC;
    for (int kt = 0; kt < 64; kt++) {
        int buf = kt & 1;
        if (kt < 63) {
            GLOAD(buf ^ 1, (kt + 1) * 32);
            CPC;
            CPW(1);
        } else {
            CPW(0);
        }
        __syncthreads();
#pragma unroll
        for (int ks = 0; ks < 32; ks += 16) {
            uint32_t a[4][4], b[4][2];
#pragma unroll
            for (int am = 0; am < 4; am++) {
                uint32_t ad = sptr(&As[buf][(wm + am * 16 + (lane & 15)) * 40 + ks + ((lane >> 4) << 3)]);
                LDSM4(a[am][0], a[am][1], a[am][2], a[am][3], ad);
            }
#pragma unroll
            for (int bp = 0; bp < 2; bp++) {
                int g = lane >> 3;
                int nr = wn + bp * 16 + (lane & 7) + ((g >> 1) << 3);
                int kc = ks + ((g & 1) << 3);
                uint32_t ad = sptr(&Bs[buf][nr * 40 + kc]);
                uint32_t r0, r1, r2, r3;
                LDSM4(r0, r1, r2, r3, ad);
                b[2 * bp][0] = r0; b[2 * bp][1] = r1;
                b[2 * bp + 1][0] = r2; b[2 * bp + 1][1] = r3;
            }
#pragma unroll
            for (int am = 0; am < 4; am++)
#pragma unroll
                for (int bf = 0; bf < 4; bf++) MMAB(acc[am][bf], a[am], b[bf]);
        }
        __syncthreads();
    }
    float sw = g_s[mat] * (1.0f / QBF);
#pragma unroll
    for (int am = 0; am < 4; am++) {
        int r0 = bm + wm + am * 16 + (lane >> 2);
        float s0 = gv[r0] * sw, s1 = gv[r0 + 8] * sw;
#pragma unroll
        for (int bf = 0; bf < 4; bf++) {
            int cc = bn + wn + bf * 8 + ((lane & 3) << 1);
            float* p0 = C + (size_t)r0 * HID + cc;
            p0[0] = acc[am][bf][0] * s0;
            p0[1] = acc[am][bf][1] * s0;
            float* p1 = p0 + (size_t)8 * HID;
            p1[0] = acc[am][bf][2] * s1;
            p1[1] = acc[am][bf][3] * s1;
        }
    }
}

// RoPE via table, out-of-place
__global__ __launch_bounds__(256) void k_rope() {
    int tok = blockIdx.x;
    int s = tok & (SEQ - 1);
    size_t tb = (size_t)tok * HID;
    for (int idx = threadIdx.x; idx < HID; idx += 256) {
        int d = idx & 127;
        int dp = d & 63;
        int partner = (idx & ~127) | ((d + 64) & 127);
        float c = g_tc[s * 64 + dp];
        float sn = g_ts[s * 64 + dp];
        float sgn = (d < 64) ? -sn : sn;
        g_qr[tb + idx] = g_q[tb + idx] * c + g_q[tb + partner] * sgn;
        g_kr[tb + idx] = g_k[tb + idx] * c + g_k[tb + partner] * sgn;
    }
}

// flash attention: warp owns 8 q-rows; all softmax state in registers
#define KSTR 129
#define ATTN_SMEM ((64 * 128 + 2 * 64 * KSTR) * 4)
__global__ __launch_bounds__(256) void k_attn() {
    extern __shared__ float sm[];
    float* Qs = sm;
    float* Ks = Qs + 64 * 128;
    float* Vs = Ks + 64 * KSTR;
    int h = blockIdx.x, b = blockIdx.y, q0 = blockIdx.z * 64;
    int tid = threadIdx.x, w = tid >> 5, l = tid & 31;
    const float scale = 0.08838834764831845f;
    size_t qb = ((size_t)(b * SEQ + q0)) * HID + h * HD;
    for (int e = tid; e < 64 * 32; e += 256) {
        int r = e >> 5, c4 = (e & 31) << 2;
        *(float4*)&Qs[r * 128 + c4] = *(const float4*)(g_qr + qb + (size_t)r * HID + c4);
    }
    float m8[8], l8[8], o[8][4];
#pragma unroll
    for (int r = 0; r < 8; r++) {
        m8[r] = -1e30f;
        l8[r] = 0.f;
#pragma unroll
        for (int j = 0; j < 4; j++) o[r][j] = 0.f;
    }
    for (int kt = 0; kt < SEQ / 64; kt++) {
        __syncthreads();
        size_t kb = ((size_t)(b * SEQ + kt * 64)) * HID + h * HD;
        for (int e = tid; e < 64 * 32; e += 256) {
            int r = e >> 5, c4 = (e & 31) << 2;
            float4 kv = *(const float4*)(g_kr + kb + (size_t)r * HID + c4);
            float4 vv = *(const float4*)(g_v + kb + (size_t)r * HID + c4);
            Ks[r * KSTR + c4] = kv.x; Ks[r * KSTR + c4 + 1] = kv.y;
            Ks[r * KSTR + c4 + 2] = kv.z; Ks[r * KSTR + c4 + 3] = kv.w;
            Vs[r * KSTR + c4] = vv.x; Vs[r * KSTR + c4 + 1] = vv.y;
            Vs[r * KSTR + c4 + 2] = vv.z; Vs[r * KSTR + c4 + 3] = vv.w;
        }
        __syncthreads();
        float a0[8], a1[8];
#pragma unroll
        for (int r = 0; r < 8; r++) { a0[r] = 0.f; a1[r] = 0.f; }
#pragma unroll 4
        for (int d = 0; d < HD; d++) {
            float k0 = Ks[l * KSTR + d];
            float k1 = Ks[(l + 32) * KSTR + d];
#pragma unroll
            for (int r = 0; r < 8; r++) {
                float qv = Qs[(w * 8 + r) * 128 + d];
                a0[r] = fmaf(qv, k0, a0[r]);
                a1[r] = fmaf(qv, k1, a1[r]);
            }
        }
#pragma unroll
        for (int r = 0; r < 8; r++) {
            float mx = fmaxf(a0[r], a1[r]);
#pragma unroll
            for (int st = 16; st > 0; st >>= 1)
                mx = fmaxf(mx, __shfl_xor_sync(0xffffffffu, mx, st));
            float mn = fmaxf(m8[r], mx * scale);
            float p0 = __expf(fmaf(a0[r], scale, -mn));
            float p1 = __expf(fmaf(a1[r], scale, -mn));
            float ts = p0 + p1;
#pragma unroll
            for (int st = 16; st > 0; st >>= 1)
                ts += __shfl_xor_sync(0xffffffffu, ts, st);
            float co = __expf(m8[r] - mn);
            m8[r] = mn;
            l8[r] = l8[r] * co + ts;
#pragma unroll
            for (int j = 0; j < 4; j++) o[r][j] *= co;
            a0[r] = p0;
            a1[r] = p1;
        }
#pragma unroll 4
        for (int k = 0; k < 32; k++) {
            float vv[4];
#pragma unroll
            for (int j = 0; j < 4; j++) vv[j] = Vs[k * KSTR + l + 32 * j];
#pragma unroll
            for (int r = 0; r < 8; r++) {
                float pv = __shfl_sync(0xffffffffu, a0[r], k);
#pragma unroll
                for (int j = 0; j < 4; j++) o[r][j] = fmaf(pv, vv[j], o[r][j]);
            }
        }
#pragma unroll 4
        for (int k = 0; k < 32; k++) {
            float vv[4];
#pragma unroll
            for (int j = 0; j < 4; j++) vv[j] = Vs[(k + 32) * KSTR + l + 32 * j];
#pragma unroll
            for (int r = 0; r < 8; r++) {
                float pv = __shfl_sync(0xffffffffu, a1[r], k);
#pragma unroll
                for (int j = 0; j < 4; j++) o[r][j] = fmaf(pv, vv[j], o[r][j]);
            }
        }
    }
#pragma unroll
    for (int r = 0; r < 8; r++) {
        float inv = 1.f / l8[r];
        float* dst = g_ctx + ((size_t)(b * SEQ + q0 + w * 8 + r)) * HID + h * HD;
#pragma unroll
        for (int j = 0; j < 4; j++) dst[l + 32 * j] = o[r][j] * inv;
    }
}

extern "C" void kernel_launch(void* const* d_in, const int* in_sizes, int n_in,
                              void* d_out, int out_size) {
    const float* x = (const float*)d_in[0];
    const float* wq = (const float*)d_in[1];
    const float* wk = (const float*)d_in[2];
    const float* wv = (const float*)d_in[3];
    const float* wo = (const float*)d_in[4];
    float* out = (float*)d_out;
    cudaFuncSetAttribute(k_attn, cudaFuncAttributeMaxDynamicSharedMemorySize, ATTN_SMEM);
    k_tab<<<256, 512>>>();
    k_wabs_partial<<<dim3(64, 4), 256>>>(wq, wk, wv, wo);
    k_wabs_final<<<4, 64>>>();
    k_quant_w<<<dim3(HID * HID / 1024, 4), 256>>>(wq, wk, wv, wo);
    k_quant_act<<<TOK, 256>>>(x, 0);
    k_gemm<<<dim3(16, 32), 256>>>(0, out);
    k_gemm<<<dim3(16, 32), 256>>>(1, out);
    k_gemm<<<dim3(16, 32), 256>>>(2, out);
    k_rope<<<TOK, 256>>>();
    k_attn<<<dim3(NH, 2, SEQ / 64), 256, ATTN_SMEM>>>();
    k_quant_act<<<TOK, 256>>>(nullptr, 1);
    k_gemm<<<dim3(16, 32), 256>>>(3, out);
}

// round 6
// speedup vs baseline: 1.2174x; 1.2174x over previous
#include <cuda_runtime.h>
#include <cuda_bf16.h>
#include <math.h>
#include <stdint.h>

#define HID 2048
#define TOK 4096
#define NH 16
#define HD 128
#define SEQ 2048
#define QBF 127.0f

__device__ __nv_bfloat16 g_w8[4][HID * HID];
__device__ float g_s[4];
__device__ float g_part[4 * 64];
__device__ __nv_bfloat16 g_x8[TOK * HID];
__device__ float g_xg[TOK];
__device__ float g_q[TOK * HID];
__device__ float g_k[TOK * HID];
__device__ float g_v[TOK * HID];
__device__ float g_qr[TOK * HID];
__device__ float g_kr[TOK * HID];
__device__ float g_ctx[TOK * HID];
__device__ __nv_bfloat16 g_c8[TOK * HID];
__device__ float g_cg[TOK];
__device__ float g_tc[SEQ * 64];
__device__ float g_ts[SEQ * 64];

__device__ __forceinline__ uint32_t sptr(const void* p) {
    return (uint32_t)__cvta_generic_to_shared(p);
}

#define CP16(s, g) asm volatile("cp.async.ca.shared.global [%0], [%1], 16;\n" ::"r"(s), "l"(g))
#define CPC asm volatile("cp.async.commit_group;\n")
#define CPW(n) asm volatile("cp.async.wait_group %0;\n" ::"n"(n))
#define LDSM4(r0, r1, r2, r3, a)                                                        \
    asm volatile("ldmatrix.sync.aligned.m8n8.x4.shared.b16 {%0,%1,%2,%3}, [%4];\n"      \
                 : "=r"(r0), "=r"(r1), "=r"(r2), "=r"(r3) : "r"(a))
#define MMAB(d, a, b)                                                                   \
    asm volatile("mma.sync.aligned.m16n8k16.row.col.f32.bf16.bf16.f32 "                 \
                 "{%0,%1,%2,%3},{%4,%5,%6,%7},{%8,%9},{%0,%1,%2,%3};\n"                 \
                 : "+f"(d[0]), "+f"(d[1]), "+f"(d[2]), "+f"(d[3])                       \
                 : "r"(a[0]), "r"(a[1]), "r"(a[2]), "r"(a[3]), "r"(b[0]), "r"(b[1]))
#define MMAT(d, a0, a1, a2, a3, b0, b1)                                                 \
    asm volatile("mma.sync.aligned.m16n8k8.row.col.f32.tf32.tf32.f32 "                  \
                 "{%0,%1,%2,%3},{%4,%5,%6,%7},{%8,%9},{%0,%1,%2,%3};\n"                 \
                 : "+f"(d[0]), "+f"(d[1]), "+f"(d[2]), "+f"(d[3])                       \
                 : "r"(a0), "r"(a1), "r"(a2), "r"(a3), "r"(b0), "r"(b1))

__device__ __forceinline__ void tf32s(float x, uint32_t& hi, uint32_t& lo) {
    uint32_t h;
    asm("cvt.rna.tf32.f32 %0, %1;" : "=r"(h) : "f"(x));
    float lf = x - __uint_as_float(h);
    uint32_t l;
    asm("cvt.rna.tf32.f32 %0, %1;" : "=r"(l) : "f"(lf));
    hi = h;
    lo = l;
}

// rope table: exact trig of the reference's fp32-rounded angle
__global__ __launch_bounds__(512) void k_tab() {
    int i = blockIdx.x * 512 + threadIdx.x;
    int s = i >> 6, dp = i & 63;
    float ff = (float)pow(10000.0, -(double)dp / 64.0);
    float angf = (float)s * ff;
    double ang = fmod((double)angf, 6.283185307179586476925287);
    g_tc[i] = (float)cos(ang);
    g_ts[i] = (float)sin(ang);
}

__global__ __launch_bounds__(256) void k_wabs_partial(const float* __restrict__ w0,
        const float* __restrict__ w1, const float* __restrict__ w2, const float* __restrict__ w3) {
    const float* w = (blockIdx.y == 0) ? w0 : (blockIdx.y == 1) ? w1 : (blockIdx.y == 2) ? w2 : w3;
    const float4* w4 = (const float4*)(w + (size_t)blockIdx.x * 65536);
    float s = 0.f;
    for (int i = threadIdx.x; i < 16384; i += 256) {
        float4 v = w4[i];
        s += fabsf(v.x) + fabsf(v.y) + fabsf(v.z) + fabsf(v.w);
    }
    __shared__ float red[256];
    red[threadIdx.x] = s;
    __syncthreads();
    for (int st = 128; st > 0; st >>= 1) {
        if (threadIdx.x < st) red[threadIdx.x] += red[threadIdx.x + st];
        __syncthreads();
    }
    if (threadIdx.x == 0) g_part[blockIdx.y * 64 + blockIdx.x] = red[0];
}

__global__ __launch_bounds__(64) void k_wabs_final() {
    __shared__ float red[64];
    red[threadIdx.x] = g_part[blockIdx.x * 64 + threadIdx.x];
    __syncthreads();
    for (int st = 32; st > 0; st >>= 1) {
        if (threadIdx.x < st) red[threadIdx.x] += red[threadIdx.x + st];
        __syncthreads();
    }
    if (threadIdx.x == 0) g_s[blockIdx.x] = red[0] / (float)(HID * HID) + 1e-5f;
}

__global__ __launch_bounds__(256) void k_quant_w(const float* __restrict__ w0,
        const float* __restrict__ w1, const float* __restrict__ w2, const float* __restrict__ w3) {
    int m = blockIdx.y;
    const float* w = (m == 0) ? w0 : (m == 1) ? w1 : (m == 2) ? w2 : w3;
    float s = g_s[m];
    int idx = (blockIdx.x * 256 + threadIdx.x) * 4;
    float4 v = *(const float4*)(w + idx);
    float qx = fminf(1.f, fmaxf(-1.f, rintf(v.x / s)));
    float qy = fminf(1.f, fmaxf(-1.f, rintf(v.y / s)));
    float qz = fminf(1.f, fmaxf(-1.f, rintf(v.z / s)));
    float qw = fminf(1.f, fmaxf(-1.f, rintf(v.w / s)));
    __nv_bfloat162 lo = __floats2bfloat162_rn(qx, qy);
    __nv_bfloat162 hi = __floats2bfloat162_rn(qz, qw);
    uint2 pk;
    pk.x = *(unsigned int*)&lo;
    pk.y = *(unsigned int*)&hi;
    *(uint2*)&g_w8[m][idx] = pk;
}

__global__ __launch_bounds__(256) void k_quant_act(const float* __restrict__ ext, int use_ctx) {
    int row = blockIdx.x;
    const float* src = use_ctx ? g_ctx : ext;
    __nv_bfloat16* dst = use_ctx ? g_c8 : g_x8;
    float* gout = use_ctx ? g_cg : g_xg;
    const float4* xr = (const float4*)(src + (size_t)row * HID);
    float4 v0 = xr[threadIdx.x];
    float4 v1 = xr[threadIdx.x + 256];
    float mx = fmaxf(fmaxf(fabsf(v0.x), fabsf(v0.y)), fmaxf(fabsf(v0.z), fabsf(v0.w)));
    mx = fmaxf(mx, fmaxf(fmaxf(fabsf(v1.x), fabsf(v1.y)), fmaxf(fabsf(v1.z), fabsf(v1.w))));
    __shared__ float red[256];
    red[threadIdx.x] = mx;
    __syncthreads();
    for (int st = 128; st > 0; st >>= 1) {
        if (threadIdx.x < st) red[threadIdx.x] = fmaxf(red[threadIdx.x], red[threadIdx.x + st]);
        __syncthreads();
    }
    float g = red[0] + 1e-5f;
    if (threadIdx.x == 0) gout[row] = g;
    float t = QBF / g;
    __nv_bfloat16* orow = dst + (size_t)row * HID;
    float4 vv[2] = {v0, v1};
    int offs[2] = {(int)threadIdx.x * 4, ((int)threadIdx.x + 256) * 4};
#pragma unroll
    for (int hh = 0; hh < 2; ++hh) {
        float a = fminf(QBF, fmaxf(-QBF, rintf(vv[hh].x * t)));
        float b = fminf(QBF, fmaxf(-QBF, rintf(vv[hh].y * t)));
        float c = fminf(QBF, fmaxf(-QBF, rintf(vv[hh].z * t)));
        float d = fminf(QBF, fmaxf(-QBF, rintf(vv[hh].w * t)));
        __nv_bfloat162 lo = __floats2bfloat162_rn(a, b);
        __nv_bfloat162 hi = __floats2bfloat162_rn(c, d);
        uint2 pk;
        pk.x = *(unsigned int*)&lo;
        pk.y = *(unsigned int*)&hi;
        *(uint2*)&orow[offs[hh]] = pk;
    }
}

__global__ __launch_bounds__(256) void k_gemm(int mat, float* __restrict__ dout) {
    __shared__ __nv_bfloat16 As[2][128 * 40];
    __shared__ __nv_bfloat16 Bs[2][128 * 40];
    const __nv_bfloat16* A = (mat == 3) ? g_c8 : g_x8;
    const float* gv = (mat == 3) ? g_cg : g_xg;
    const __nv_bfloat16* W = g_w8[mat];
    float* C = (mat == 0) ? g_q : (mat == 1) ? g_k : (mat == 2) ? g_v : dout;
    int tid = threadIdx.x;
    int bm = blockIdx.y * 128, bn = blockIdx.x * 128;
    int warp = tid >> 5, lane = tid & 31;
    int wm = (warp >> 2) * 64, wn = (warp & 3) * 32;
    float acc[4][4][4];
#pragma unroll
    for (int i = 0; i < 4; i++)
#pragma unroll
        for (int j = 0; j < 4; j++)
#pragma unroll
            for (int r = 0; r < 4; r++) acc[i][j][r] = 0.f;
    const __nv_bfloat16* Ab = A + (size_t)bm * HID;
    const __nv_bfloat16* Wb = W + (size_t)bn * HID;
#define GLOAD(bf, k0)                                                              \
    for (int c = tid; c < 512; c += 256) {                                         \
        int rr = c >> 2, kc = (c & 3) << 3;                                        \
        CP16(sptr(&As[bf][rr * 40 + kc]), Ab + (size_t)rr * HID + (k0) + kc);      \
        CP16(sptr(&Bs[bf][rr * 40 + kc]), Wb + (size_t)rr * HID + (k0) + kc);      \
    }
    GLOAD(0, 0);
    CPC;
    for (int kt = 0; kt < 64; kt++) {
        int buf = kt & 1;
        if (kt < 63) {
            GLOAD(buf ^ 1, (kt + 1) * 32);
            CPC;
            CPW(1);
        } else {
            CPW(0);
        }
        __syncthreads();
#pragma unroll
        for (int ks = 0; ks < 32; ks += 16) {
            uint32_t a[4][4], b[4][2];
#pragma unroll
            for (int am = 0; am < 4; am++) {
                uint32_t ad = sptr(&As[buf][(wm + am * 16 + (lane & 15)) * 40 + ks + ((lane >> 4) << 3)]);
                LDSM4(a[am][0], a[am][1], a[am][2], a[am][3], ad);
            }
#pragma unroll
            for (int bp = 0; bp < 2; bp++) {
                int g = lane >> 3;
                int nr = wn + bp * 16 + (lane & 7) + ((g >> 1) << 3);
                int kc = ks + ((g & 1) << 3);
                uint32_t ad = sptr(&Bs[buf][nr * 40 + kc]);
                uint32_t r0, r1, r2, r3;
                LDSM4(r0, r1, r2, r3, ad);
                b[2 * bp][0] = r0; b[2 * bp][1] = r1;
                b[2 * bp + 1][0] = r2; b[2 * bp + 1][1] = r3;
            }
#pragma unroll
            for (int am = 0; am < 4; am++)
#pragma unroll
                for (int bf = 0; bf < 4; bf++) MMAB(acc[am][bf], a[am], b[bf]);
        }
        __syncthreads();
    }
    float sw = g_s[mat] * (1.0f / QBF);
#pragma unroll
    for (int am = 0; am < 4; am++) {
        int r0 = bm + wm + am * 16 + (lane >> 2);
        float s0 = gv[r0] * sw, s1 = gv[r0 + 8] * sw;
#pragma unroll
        for (int bf = 0; bf < 4; bf++) {
            int cc = bn + wn + bf * 8 + ((lane & 3) << 1);
            float* p0 = C + (size_t)r0 * HID + cc;
            p0[0] = acc[am][bf][0] * s0;
            p0[1] = acc[am][bf][1] * s0;
            float* p1 = p0 + (size_t)8 * HID;
            p1[0] = acc[am][bf][2] * s1;
            p1[1] = acc[am][bf][3] * s1;
        }
    }
}

// RoPE via table, out-of-place
__global__ __launch_bounds__(256) void k_rope() {
    int tok = blockIdx.x;
    int s = tok & (SEQ - 1);
    size_t tb = (size_t)tok * HID;
    for (int idx = threadIdx.x; idx < HID; idx += 256) {
        int d = idx & 127;
        int dp = d & 63;
        int partner = (idx & ~127) | ((d + 64) & 127);
        float c = g_tc[s * 64 + dp];
        float sn = g_ts[s * 64 + dp];
        float sgn = (d < 64) ? -sn : sn;
        g_qr[tb + idx] = g_q[tb + idx] * c + g_q[tb + partner] * sgn;
        g_kr[tb + idx] = g_k[tb + idx] * c + g_k[tb + partner] * sgn;
    }
}

// flash attention on tensor cores: split-TF32 (3xTF32) for fp32-level accuracy.
// CTA: 256 threads (8 warps). Q-tile 128 rows (16/warp), K-tile 64 keys.
#define QST 132
#define KSA 132
#define KSB 136
#define PST 68
#define ATTN_SMEM ((128 * QST + 64 * KSA + 64 * KSB + 128 * PST) * 4)
__global__ __launch_bounds__(256) void k_attn() {
    extern __shared__ float sm[];
    float* Qs = sm;                    // [128][QST] raw fp32 Q
    float* Ks = Qs + 128 * QST;        // [64][KSA]
    float* Vs = Ks + 64 * KSA;         // [64][KSB]
    float* Ps = Vs + 64 * KSB;         // [128][PST] per-warp P slabs
    int h = blockIdx.x, b = blockIdx.y, q0 = blockIdx.z * 128;
    int tid = threadIdx.x, w = tid >> 5, lane = tid & 31;
    int gr = lane >> 2, gc = lane & 3;
    const float scale = 0.08838834764831845f;
    size_t qb = ((size_t)(b * SEQ + q0)) * HID + h * HD;
    for (int e = tid; e < 128 * 32; e += 256) {
        int r = e >> 5, c4 = (e & 31) << 2;
        float4 v = *(const float4*)(g_qr + qb + (size_t)r * HID + c4);
        float* p = &Qs[r * QST + c4];
        p[0] = v.x; p[1] = v.y; p[2] = v.z; p[3] = v.w;
    }
    float o[16][4];
#pragma unroll
    for (int i = 0; i < 16; i++) { o[i][0] = o[i][1] = o[i][2] = o[i][3] = 0.f; }
    float m_lo = -1e30f, m_hi = -1e30f, l_lo = 0.f, l_hi = 0.f;
    int wr = w * 16;
    float* Pw = Ps + wr * PST;
    const int r_lo = wr + gr, r_hi = wr + gr + 8;
    for (int kt = 0; kt < SEQ / 64; kt++) {
        __syncthreads();
        size_t kb0 = ((size_t)(b * SEQ + kt * 64)) * HID + h * HD;
        for (int e = tid; e < 64 * 32; e += 256) {
            int r = e >> 5, c4 = (e & 31) << 2;
            float4 kv = *(const float4*)(g_kr + kb0 + (size_t)r * HID + c4);
            float4 vv = *(const float4*)(g_v + kb0 + (size_t)r * HID + c4);
            float* pk = &Ks[r * KSA + c4];
            pk[0] = kv.x; pk[1] = kv.y; pk[2] = kv.z; pk[3] = kv.w;
            float* pv = &Vs[r * KSB + c4];
            pv[0] = vv.x; pv[1] = vv.y; pv[2] = vv.z; pv[3] = vv.w;
        }
        __syncthreads();
        float c[8][4];
#pragma unroll
        for (int j = 0; j < 8; j++) { c[j][0] = c[j][1] = c[j][2] = c[j][3] = 0.f; }
        for (int ks = 0; ks < 16; ks++) {
            int kb = ks * 8;
            uint32_t ah[4], al[4];
            tf32s(Qs[r_lo * QST + kb + gc], ah[0], al[0]);
            tf32s(Qs[r_hi * QST + kb + gc], ah[1], al[1]);
            tf32s(Qs[r_lo * QST + kb + gc + 4], ah[2], al[2]);
            tf32s(Qs[r_hi * QST + kb + gc + 4], ah[3], al[3]);
#pragma unroll
            for (int nb = 0; nb < 8; nb++) {
                uint32_t bh[2], bl[2];
                tf32s(Ks[(nb * 8 + gr) * KSA + kb + gc], bh[0], bl[0]);
                tf32s(Ks[(nb * 8 + gr) * KSA + kb + gc + 4], bh[1], bl[1]);
                MMAT(c[nb], ah[0], ah[1], ah[2], ah[3], bh[0], bh[1]);
                MMAT(c[nb], ah[0], ah[1], ah[2], ah[3], bl[0], bl[1]);
                MMAT(c[nb], al[0], al[1], al[2], al[3], bh[0], bh[1]);
            }
        }
        // online softmax on fragments (rows gr -> c0,c1 ; gr+8 -> c2,c3)
        float mx_lo = -1e30f, mx_hi = -1e30f;
#pragma unroll
        for (int j = 0; j < 8; j++) {
            mx_lo = fmaxf(mx_lo, fmaxf(c[j][0], c[j][1]));
            mx_hi = fmaxf(mx_hi, fmaxf(c[j][2], c[j][3]));
        }
        mx_lo = fmaxf(mx_lo, __shfl_xor_sync(0xffffffffu, mx_lo, 1));
        mx_lo = fmaxf(mx_lo, __shfl_xor_sync(0xffffffffu, mx_lo, 2));
        mx_hi = fmaxf(mx_hi, __shfl_xor_sync(0xffffffffu, mx_hi, 1));
        mx_hi = fmaxf(mx_hi, __shfl_xor_sync(0xffffffffu, mx_hi, 2));
        float mn_lo = fmaxf(m_lo, mx_lo * scale);
        float mn_hi = fmaxf(m_hi, mx_hi * scale);
        float ts_lo = 0.f, ts_hi = 0.f;
#pragma unroll
        for (int j = 0; j < 8; j++) {
            c[j][0] = __expf(fmaf(c[j][0], scale, -mn_lo));
            c[j][1] = __expf(fmaf(c[j][1], scale, -mn_lo));
            c[j][2] = __expf(fmaf(c[j][2], scale, -mn_hi));
            c[j][3] = __expf(fmaf(c[j][3], scale, -mn_hi));
            ts_lo += c[j][0] + c[j][1];
            ts_hi += c[j][2] + c[j][3];
        }
        ts_lo += __shfl_xor_sync(0xffffffffu, ts_lo, 1);
        ts_lo += __shfl_xor_sync(0xffffffffu, ts_lo, 2);
        ts_hi += __shfl_xor_sync(0xffffffffu, ts_hi, 1);
        ts_hi += __shfl_xor_sync(0xffffffffu, ts_hi, 2);
        float co_lo = __expf(m_lo - mn_lo), co_hi = __expf(m_hi - mn_hi);
        m_lo = mn_lo; m_hi = mn_hi;
        l_lo = l_lo * co_lo + ts_lo;
        l_hi = l_hi * co_hi + ts_hi;
#pragma unroll
        for (int j = 0; j < 16; j++) {
            o[j][0] *= co_lo; o[j][1] *= co_lo;
            o[j][2] *= co_hi; o[j][3] *= co_hi;
        }
        // stash P in per-warp smem slab (C-layout -> A-layout transpose)
#pragma unroll
        for (int j = 0; j < 8; j++) {
            *(float2*)&Pw[gr * PST + j * 8 + 2 * gc] = make_float2(c[j][0], c[j][1]);
            *(float2*)&Pw[(gr + 8) * PST + j * 8 + 2 * gc] = make_float2(c[j][2], c[j][3]);
        }
        __syncwarp();
        // P @ V
        for (int ks = 0; ks < 8; ks++) {
            int kb = ks * 8;
            uint32_t ah[4], al[4];
            tf32s(Pw[gr * PST + kb + gc], ah[0], al[0]);
            tf32s(Pw[(gr + 8) * PST + kb + gc], ah[1], al[1]);
            tf32s(Pw[gr * PST + kb + gc + 4], ah[2], al[2]);
            tf32s(Pw[(gr + 8) * PST + kb + gc + 4], ah[3], al[3]);
#pragma unroll
            for (int nb = 0; nb < 16; nb++) {
                uint32_t bh[2], bl[2];
                tf32s(Vs[(kb + gc) * KSB + nb * 8 + gr], bh[0], bl[0]);
                tf32s(Vs[(kb + gc + 4) * KSB + nb * 8 + gr], bh[1], bl[1]);
                MMAT(o[nb], ah[0], ah[1], ah[2], ah[3], bh[0], bh[1]);
                MMAT(o[nb], ah[0], ah[1], ah[2], ah[3], bl[0], bl[1]);
                MMAT(o[nb], al[0], al[1], al[2], al[3], bh[0], bh[1]);
            }
        }
    }
    float inv_lo = 1.f / l_lo, inv_hi = 1.f / l_hi;
    float* d_lo = g_ctx + ((size_t)(b * SEQ + q0 + r_lo)) * HID + h * HD;
    float* d_hi = g_ctx + ((size_t)(b * SEQ + q0 + r_hi)) * HID + h * HD;
#pragma unroll
    for (int nb = 0; nb < 16; nb++) {
        *(float2*)&d_lo[nb * 8 + 2 * gc] = make_float2(o[nb][0] * inv_lo, o[nb][1] * inv_lo);
        *(float2*)&d_hi[nb * 8 + 2 * gc] = make_float2(o[nb][2] * inv_hi, o[nb][3] * inv_hi);
    }
}

extern "C" void kernel_launch(void* const* d_in, const int* in_sizes, int n_in,
                              void* d_out, int out_size) {
    const float* x = (const float*)d_in[0];
    const float* wq = (const float*)d_in[1];
    const float* wk = (const float*)d_in[2];
    const float* wv = (const float*)d_in[3];
    const float* wo = (const float*)d_in[4];
    float* out = (float*)d_out;
    cudaFuncSetAttribute(k_attn, cudaFuncAttributeMaxDynamicSharedMemorySize, ATTN_SMEM);
    k_tab<<<256, 512>>>();
    k_wabs_partial<<<dim3(64, 4), 256>>>(wq, wk, wv, wo);
    k_wabs_final<<<4, 64>>>();
    k_quant_w<<<dim3(HID * HID / 1024, 4), 256>>>(wq, wk, wv, wo);
    k_quant_act<<<TOK, 256>>>(x, 0);
    k_gemm<<<dim3(16, 32), 256>>>(0, out);
    k_gemm<<<dim3(16, 32), 256>>>(1, out);
    k_gemm<<<dim3(16, 32), 256>>>(2, out);
    k_rope<<<TOK, 256>>>();
    k_attn<<<dim3(NH, 2, SEQ / 128), 256, ATTN_SMEM>>>();
    k_quant_act<<<TOK, 256>>>(nullptr, 1);
    k_gemm<<<dim3(16, 32), 256>>>(3, out);
}

// round 8
// speedup vs baseline: 1.7792x; 1.4614x over previous
#include <cuda_runtime.h>
#include <cuda_bf16.h>
#include <cuda_fp16.h>
#include <math.h>
#include <stdint.h>

#define HID 2048
#define TOK 4096
#define NH 16
#define HD 128
#define SEQ 2048
#define QBF 127.0f

__device__ __nv_bfloat16 g_w8[4][HID * HID];
__device__ float g_s[4];
__device__ float g_part[4 * 64];
__device__ __nv_bfloat16 g_x8[TOK * HID];
__device__ float g_xg[TOK];
__device__ float g_q[TOK * HID];
__device__ float g_k[TOK * HID];
__device__ float g_v[TOK * HID];
__device__ float g_qr[TOK * HID];
__device__ float g_kr[TOK * HID];
__device__ float g_vt[TOK * HID];
__device__ float g_ctx[TOK * HID];
__device__ __nv_bfloat16 g_c8[TOK * HID];
__device__ float g_cg[TOK];
__device__ float g_tc[SEQ * 64];
__device__ float g_ts[SEQ * 64];

__device__ __forceinline__ uint32_t sptr(const void* p) {
    return (uint32_t)__cvta_generic_to_shared(p);
}

#define CP16(s, g) asm volatile("cp.async.ca.shared.global [%0], [%1], 16;\n" ::"r"(s), "l"(g))
#define CPC asm volatile("cp.async.commit_group;\n")
#define CPW(n) asm volatile("cp.async.wait_group %0;\n" ::"n"(n))
#define LDSM4(r0, r1, r2, r3, a)                                                        \
    asm volatile("ldmatrix.sync.aligned.m8n8.x4.shared.b16 {%0,%1,%2,%3}, [%4];\n"      \
                 : "=r"(r0), "=r"(r1), "=r"(r2), "=r"(r3) : "r"(a))
#define MMAB(d, a, b)                                                                   \
    asm volatile("mma.sync.aligned.m16n8k16.row.col.f32.bf16.bf16.f32 "                 \
                 "{%0,%1,%2,%3},{%4,%5,%6,%7},{%8,%9},{%0,%1,%2,%3};\n"                 \
                 : "+f"(d[0]), "+f"(d[1]), "+f"(d[2]), "+f"(d[3])                       \
                 : "r"(a[0]), "r"(a[1]), "r"(a[2]), "r"(a[3]), "r"(b[0]), "r"(b[1]))
#define MMAH(d, a0, a1, a2, a3, b0, b1)                                                 \
    asm volatile("mma.sync.aligned.m16n8k16.row.col.f32.f16.f16.f32 "                   \
                 "{%0,%1,%2,%3},{%4,%5,%6,%7},{%8,%9},{%0,%1,%2,%3};\n"                 \
                 : "+f"(d[0]), "+f"(d[1]), "+f"(d[2]), "+f"(d[3])                       \
                 : "r"(a0), "r"(a1), "r"(a2), "r"(a3), "r"(b0), "r"(b1))

// split (x,y) into packed-half2 hi + lo with hi+lo == x (to fp16x2 precision)
__device__ __forceinline__ void h2split(float x, float y, uint32_t& hi, uint32_t& lo) {
    __half2 h = __floats2half2_rn(x, y);
    float2 hf = __half22float2(h);
    __half2 l = __floats2half2_rn(x - hf.x, y - hf.y);
    hi = *(uint32_t*)&h;
    lo = *(uint32_t*)&l;
}

// rope table: exact trig of the reference's fp32-rounded angle
__global__ __launch_bounds__(512) void k_tab() {
    int i = blockIdx.x * 512 + threadIdx.x;
    int s = i >> 6, dp = i & 63;
    float ff = (float)pow(10000.0, -(double)dp / 64.0);
    float angf = (float)s * ff;
    double ang = fmod((double)angf, 6.283185307179586476925287);
    g_tc[i] = (float)cos(ang);
    g_ts[i] = (float)sin(ang);
}

__global__ __launch_bounds__(256) void k_wabs_partial(const float* __restrict__ w0,
        const float* __restrict__ w1, const float* __restrict__ w2, const float* __restrict__ w3) {
    const float* w = (blockIdx.y == 0) ? w0 : (blockIdx.y == 1) ? w1 : (blockIdx.y == 2) ? w2 : w3;
    const float4* w4 = (const float4*)(w + (size_t)blockIdx.x * 65536);
    float s = 0.f;
    for (int i = threadIdx.x; i < 16384; i += 256) {
        float4 v = w4[i];
        s += fabsf(v.x) + fabsf(v.y) + fabsf(v.z) + fabsf(v.w);
    }
    __shared__ float red[256];
    red[threadIdx.x] = s;
    __syncthreads();
    for (int st = 128; st > 0; st >>= 1) {
        if (threadIdx.x < st) red[threadIdx.x] += red[threadIdx.x + st];
        __syncthreads();
    }
    if (threadIdx.x == 0) g_part[blockIdx.y * 64 + blockIdx.x] = red[0];
}

__global__ __launch_bounds__(64) void k_wabs_final() {
    __shared__ float red[64];
    red[threadIdx.x] = g_part[blockIdx.x * 64 + threadIdx.x];
    __syncthreads();
    for (int st = 32; st > 0; st >>= 1) {
        if (threadIdx.x < st) red[threadIdx.x] += red[threadIdx.x + st];
        __syncthreads();
    }
    if (threadIdx.x == 0) g_s[blockIdx.x] = red[0] / (float)(HID * HID) + 1e-5f;
}

__global__ __launch_bounds__(256) void k_quant_w(const float* __restrict__ w0,
        const float* __restrict__ w1, const float* __restrict__ w2, const float* __restrict__ w3) {
    int m = blockIdx.y;
    const float* w = (m == 0) ? w0 : (m == 1) ? w1 : (m == 2) ? w2 : w3;
    float s = g_s[m];
    int idx = (blockIdx.x * 256 + threadIdx.x) * 4;
    float4 v = *(const float4*)(w + idx);
    float qx = fminf(1.f, fmaxf(-1.f, rintf(v.x / s)));
    float qy = fminf(1.f, fmaxf(-1.f, rintf(v.y / s)));
    float qz = fminf(1.f, fmaxf(-1.f, rintf(v.z / s)));
    float qw = fminf(1.f, fmaxf(-1.f, rintf(v.w / s)));
    __nv_bfloat162 lo = __floats2bfloat162_rn(qx, qy);
    __nv_bfloat162 hi = __floats2bfloat162_rn(qz, qw);
    uint2 pk;
    pk.x = *(unsigned int*)&lo;
    pk.y = *(unsigned int*)&hi;
    *(uint2*)&g_w8[m][idx] = pk;
}

__global__ __launch_bounds__(256) void k_quant_act(const float* __restrict__ ext, int use_ctx) {
    int row = blockIdx.x;
    const float* src = use_ctx ? g_ctx : ext;
    __nv_bfloat16* dst = use_ctx ? g_c8 : g_x8;
    float* gout = use_ctx ? g_cg : g_xg;
    const float4* xr = (const float4*)(src + (size_t)row * HID);
    float4 v0 = xr[threadIdx.x];
    float4 v1 = xr[threadIdx.x + 256];
    float mx = fmaxf(fmaxf(fabsf(v0.x), fabsf(v0.y)), fmaxf(fabsf(v0.z), fabsf(v0.w)));
    mx = fmaxf(mx, fmaxf(fmaxf(fabsf(v1.x), fabsf(v1.y)), fmaxf(fabsf(v1.z), fabsf(v1.w))));
    __shared__ float red[256];
    red[threadIdx.x] = mx;
    __syncthreads();
    for (int st = 128; st > 0; st >>= 1) {
        if (threadIdx.x < st) red[threadIdx.x] = fmaxf(red[threadIdx.x], red[threadIdx.x + st]);
        __syncthreads();
    }
    float g = red[0] + 1e-5f;
    if (threadIdx.x == 0) gout[row] = g;
    float t = QBF / g;
    __nv_bfloat16* orow = dst + (size_t)row * HID;
    float4 vv[2] = {v0, v1};
    int offs[2] = {(int)threadIdx.x * 4, ((int)threadIdx.x + 256) * 4};
#pragma unroll
    for (int hh = 0; hh < 2; ++hh) {
        float a = fminf(QBF, fmaxf(-QBF, rintf(vv[hh].x * t)));
        float b = fminf(QBF, fmaxf(-QBF, rintf(vv[hh].y * t)));
        float c = fminf(QBF, fmaxf(-QBF, rintf(vv[hh].z * t)));
        float d = fminf(QBF, fmaxf(-QBF, rintf(vv[hh].w * t)));
        __nv_bfloat162 lo = __floats2bfloat162_rn(a, b);
        __nv_bfloat162 hi = __floats2bfloat162_rn(c, d);
        uint2 pk;
        pk.x = *(unsigned int*)&lo;
        pk.y = *(unsigned int*)&hi;
        *(uint2*)&orow[offs[hh]] = pk;
    }
}

__global__ __launch_bounds__(256) void k_gemm(int mat, float* __restrict__ dout) {
    __shared__ __nv_bfloat16 As[2][128 * 40];
    __shared__ __nv_bfloat16 Bs[2][128 * 40];
    const __nv_bfloat16* A = (mat == 3) ? g_c8 : g_x8;
    const float* gv = (mat == 3) ? g_cg : g_xg;
    const __nv_bfloat16* W = g_w8[mat];
    float* C = (mat == 0) ? g_q : (mat == 1) ? g_k : (mat == 2) ? g_v : dout;
    int tid = threadIdx.x;
    int bm = blockIdx.y * 128, bn = blockIdx.x * 128;
    int warp = tid >> 5, lane = tid & 31;
    int wm = (warp >> 2) * 64, wn = (warp & 3) * 32;
    float acc[4][4][4];
#pragma unroll
    for (int i = 0; i < 4; i++)
#pragma unroll
        for (int j = 0; j < 4; j++)
#pragma unroll
            for (int r = 0; r < 4; r++) acc[i][j][r] = 0.f;
    const __nv_bfloat16* Ab = A + (size_t)bm * HID;
    const __nv_bfloat16* Wb = W + (size_t)bn * HID;
#define GLOAD(bf, k0)                                                              \
    for (int c = tid; c < 512; c += 256) {                                         \
        int rr = c >> 2, kc = (c & 3) << 3;                                        \
        CP16(sptr(&As[bf][rr * 40 + kc]), Ab + (size_t)rr * HID + (k0) + kc);      \
        CP16(sptr(&Bs[bf][rr * 40 + kc]), Wb + (size_t)rr * HID + (k0) + kc);      \
    }
    GLOAD(0, 0);
    CPC;
    for (int kt = 0; kt < 64; kt++) {
        int buf = kt & 1;
        if (kt < 63) {
            GLOAD(buf ^ 1, (kt + 1) * 32);
            CPC;
            CPW(1);
        } else {
            CPW(0);
        }
        __syncthreads();
#pragma unroll
        for (int ks = 0; ks < 32; ks += 16) {
            uint32_t a[4][4], b[4][2];
#pragma unroll
            for (int am = 0; am < 4; am++) {
                uint32_t ad = sptr(&As[buf][(wm + am * 16 + (lane & 15)) * 40 + ks + ((lane >> 4) << 3)]);
                LDSM4(a[am][0], a[am][1], a[am][2], a[am][3], ad);
            }
#pragma unroll
            for (int bp = 0; bp < 2; bp++) {
                int g = lane >> 3;
                int nr = wn + bp * 16 + (lane & 7) + ((g >> 1) << 3);
                int kc = ks + ((g & 1) << 3);
                uint32_t ad = sptr(&Bs[buf][nr * 40 + kc]);
                uint32_t r0, r1, r2, r3;
                LDSM4(r0, r1, r2, r3, ad);
                b[2 * bp][0] = r0; b[2 * bp][1] = r1;
                b[2 * bp + 1][0] = r2; b[2 * bp + 1][1] = r3;
            }
#pragma unroll
            for (int am = 0; am < 4; am++)
#pragma unroll
                for (int bf = 0; bf < 4; bf++) MMAB(acc[am][bf], a[am], b[bf]);
        }
        __syncthreads();
    }
    float sw = g_s[mat] * (1.0f / QBF);
#pragma unroll
    for (int am = 0; am < 4; am++) {
        int r0 = bm + wm + am * 16 + (lane >> 2);
        float s0 = gv[r0] * sw, s1 = gv[r0 + 8] * sw;
#pragma unroll
        for (int bf = 0; bf < 4; bf++) {
            int cc = bn + wn + bf * 8 + ((lane & 3) << 1);
            float* p0 = C + (size_t)r0 * HID + cc;
            p0[0] = acc[am][bf][0] * s0;
            p0[1] = acc[am][bf][1] * s0;
            float* p1 = p0 + (size_t)8 * HID;
            p1[0] = acc[am][bf][2] * s1;
            p1[1] = acc[am][bf][3] * s1;
        }
    }
}

// RoPE via table, out-of-place
__global__ __launch_bounds__(256) void k_rope() {
    int tok = blockIdx.x;
    int s = tok & (SEQ - 1);
    size_t tb = (size_t)tok * HID;
    for (int idx = threadIdx.x; idx < HID; idx += 256) {
        int d = idx & 127;
        int dp = d & 63;
        int partner = (idx & ~127) | ((d + 64) & 127);
        float c = g_tc[s * 64 + dp];
        float sn = g_ts[s * 64 + dp];
        float sgn = (d < 64) ? -sn : sn;
        g_qr[tb + idx] = g_q[tb + idx] * c + g_q[tb + partner] * sgn;
        g_kr[tb + idx] = g_k[tb + idx] * c + g_k[tb + partner] * sgn;
    }
}

// V transpose: g_v [b,s][h,d] -> g_vt [(b*NH+h)*HD+d][s]
__global__ __launch_bounds__(256) void k_vt() {
    __shared__ float t[32][33];
    int s0 = blockIdx.x * 32, d0 = blockIdx.y * 32;
    int h = blockIdx.z & (NH - 1), b = blockIdx.z >> 4;
    int tx = threadIdx.x, ty = threadIdx.y;
#pragma unroll
    for (int i = 0; i < 4; i++) {
        int s = s0 + ty + 8 * i;
        t[ty + 8 * i][tx] = g_v[((size_t)(b * SEQ + s)) * HID + h * HD + d0 + tx];
    }
    __syncthreads();
#pragma unroll
    for (int i = 0; i < 4; i++) {
        int d = d0 + ty + 8 * i;
        g_vt[((size_t)((b * NH + h) * HD + d)) * SEQ + s0 + tx] = t[tx][ty + 8 * i];
    }
}

// flash attention: fp16 2-term split (hi+lo), m16n8k16 MMAs, all operands
// pre-split into packed-half2 smem. Q-tile 128 (16 rows/warp), K-tile 64.
#define QST2 68
#define KST2 68
#define VST2 36
#define PST2 36
#define ATTN_SMEM ((2 * 128 * QST2 + 2 * 64 * KST2 + 2 * 128 * VST2 + 2 * 128 * PST2) * 4)
__global__ __launch_bounds__(256) void k_attn() {
    extern __shared__ uint32_t smu[];
    uint32_t* Qh = smu;                  // [128][QST2]
    uint32_t* Ql = Qh + 128 * QST2;
    uint32_t* Kh = Ql + 128 * QST2;      // [64][KST2]
    uint32_t* Kl = Kh + 64 * KST2;
    uint32_t* Vh = Kl + 64 * KST2;       // [128 dims][VST2 key-half2]
    uint32_t* Vl = Vh + 128 * VST2;
    uint32_t* Ph = Vl + 128 * VST2;      // [128 q][PST2 key-half2]
    uint32_t* Pl = Ph + 128 * PST2;
    int h = blockIdx.x, b = blockIdx.y, q0 = blockIdx.z * 128;
    int tid = threadIdx.x, w = tid >> 5, lane = tid & 31;
    int gr = lane >> 2, gc = lane & 3;
    const float scale = 0.08838834764831845f;
    // load + split Q (128 rows x 32 float4 = full 128 dims)
    size_t qb = ((size_t)(b * SEQ + q0)) * HID + h * HD;
    for (int e = tid; e < 128 * 32; e += 256) {
        int r = e >> 5, cg = e & 31;
        float4 v = *(const float4*)(g_qr + qb + (size_t)r * HID + cg * 4);
        uint32_t h0, l0, h1, l1;
        h2split(v.x, v.y, h0, l0);
        h2split(v.z, v.w, h1, l1);
        *(uint2*)&Qh[r * QST2 + 2 * cg] = make_uint2(h0, h1);
        *(uint2*)&Ql[r * QST2 + 2 * cg] = make_uint2(l0, l1);
    }
    float o[16][4];
#pragma unroll
    for (int i = 0; i < 16; i++) { o[i][0] = o[i][1] = o[i][2] = o[i][3] = 0.f; }
    float m_lo = -1e30f, m_hi = -1e30f, l_lo = 0.f, l_hi = 0.f;
    int wr = w * 16;
    const int r_lo = wr + gr, r_hi = wr + gr + 8;
    size_t vtb = ((size_t)((b * NH + h) * HD)) * SEQ;
    for (int kt = 0; kt < SEQ / 64; kt++) {
        __syncthreads();
        size_t kb0 = ((size_t)(b * SEQ + kt * 64)) * HID + h * HD;
        // K: 64 rows x 32 float4 (full 128 dims)
        for (int e = tid; e < 64 * 32; e += 256) {
            int r = e >> 5, cg = e & 31;
            float4 v = *(const float4*)(g_kr + kb0 + (size_t)r * HID + cg * 4);
            uint32_t h0, l0, h1, l1;
            h2split(v.x, v.y, h0, l0);
            h2split(v.z, v.w, h1, l1);
            *(uint2*)&Kh[r * KST2 + 2 * cg] = make_uint2(h0, h1);
            *(uint2*)&Kl[r * KST2 + 2 * cg] = make_uint2(l0, l1);
        }
        // V^T: 128 dim-rows x 16 float4 (64 keys)
        for (int e = tid; e < 128 * 16; e += 256) {
            int d = e >> 4, kg = e & 15;
            float4 v = *(const float4*)(g_vt + vtb + (size_t)d * SEQ + kt * 64 + kg * 4);
            uint32_t h0, l0, h1, l1;
            h2split(v.x, v.y, h0, l0);
            h2split(v.z, v.w, h1, l1);
            *(uint2*)&Vh[d * VST2 + 2 * kg] = make_uint2(h0, h1);
            *(uint2*)&Vl[d * VST2 + 2 * kg] = make_uint2(l0, l1);
        }
        __syncthreads();
        float c[8][4];
#pragma unroll
        for (int j = 0; j < 8; j++) { c[j][0] = c[j][1] = c[j][2] = c[j][3] = 0.f; }
#pragma unroll
        for (int ks = 0; ks < 8; ks++) {
            int cb = ks * 8;
            uint32_t ah0 = Qh[r_lo * QST2 + cb + gc], ah1 = Qh[r_hi * QST2 + cb + gc];
            uint32_t ah2 = Qh[r_lo * QST2 + cb + gc + 4], ah3 = Qh[r_hi * QST2 + cb + gc + 4];
            uint32_t al0 = Ql[r_lo * QST2 + cb + gc], al1 = Ql[r_hi * QST2 + cb + gc];
            uint32_t al2 = Ql[r_lo * QST2 + cb + gc + 4], al3 = Ql[r_hi * QST2 + cb + gc + 4];
#pragma unroll
            for (int nb = 0; nb < 8; nb++) {
                uint32_t bh0 = Kh[(nb * 8 + gr) * KST2 + cb + gc];
                uint32_t bh1 = Kh[(nb * 8 + gr) * KST2 + cb + gc + 4];
                uint32_t bl0 = Kl[(nb * 8 + gr) * KST2 + cb + gc];
                uint32_t bl1 = Kl[(nb * 8 + gr) * KST2 + cb + gc + 4];
                MMAH(c[nb], ah0, ah1, ah2, ah3, bh0, bh1);
                MMAH(c[nb], ah0, ah1, ah2, ah3, bl0, bl1);
                MMAH(c[nb], al0, al1, al2, al3, bh0, bh1);
            }
        }
        // online softmax (rows gr -> c0,c1 ; gr+8 -> c2,c3)
        float mx_lo = -1e30f, mx_hi = -1e30f;
#pragma unroll
        for (int j = 0; j < 8; j++) {
            mx_lo = fmaxf(mx_lo, fmaxf(c[j][0], c[j][1]));
            mx_hi = fmaxf(mx_hi, fmaxf(c[j][2], c[j][3]));
        }
        mx_lo = fmaxf(mx_lo, __shfl_xor_sync(0xffffffffu, mx_lo, 1));
        mx_lo = fmaxf(mx_lo, __shfl_xor_sync(0xffffffffu, mx_lo, 2));
        mx_hi = fmaxf(mx_hi, __shfl_xor_sync(0xffffffffu, mx_hi, 1));
        mx_hi = fmaxf(mx_hi, __shfl_xor_sync(0xffffffffu, mx_hi, 2));
        float mn_lo = fmaxf(m_lo, mx_lo * scale);
        float mn_hi = fmaxf(m_hi, mx_hi * scale);
        float ts_lo = 0.f, ts_hi = 0.f;
#pragma unroll
        for (int j = 0; j < 8; j++) {
            c[j][0] = __expf(fmaf(c[j][0], scale, -mn_lo));
            c[j][1] = __expf(fmaf(c[j][1], scale, -mn_lo));
            c[j][2] = __expf(fmaf(c[j][2], scale, -mn_hi));
            c[j][3] = __expf(fmaf(c[j][3], scale, -mn_hi));
            ts_lo += c[j][0] + c[j][1];
            ts_hi += c[j][2] + c[j][3];
        }
        ts_lo += __shfl_xor_sync(0xffffffffu, ts_lo, 1);
        ts_lo += __shfl_xor_sync(0xffffffffu, ts_lo, 2);
        ts_hi += __shfl_xor_sync(0xffffffffu, ts_hi, 1);
        ts_hi += __shfl_xor_sync(0xffffffffu, ts_hi, 2);
        float co_lo = __expf(m_lo - mn_lo), co_hi = __expf(m_hi - mn_hi);
        m_lo = mn_lo; m_hi = mn_hi;
        l_lo = l_lo * co_lo + ts_lo;
        l_hi = l_hi * co_hi + ts_hi;
#pragma unroll
        for (int j = 0; j < 16; j++) {
            o[j][0] *= co_lo; o[j][1] *= co_lo;
            o[j][2] *= co_hi; o[j][3] *= co_hi;
        }
        // stash P (split) — keys j*8+2gc, j*8+2gc+1 -> half2 col 4j+gc
#pragma unroll
        for (int j = 0; j < 8; j++) {
            uint32_t ph, pl;
            h2split(c[j][0], c[j][1], ph, pl);
            Ph[r_lo * PST2 + 4 * j + gc] = ph;
            Pl[r_lo * PST2 + 4 * j + gc] = pl;
            h2split(c[j][2], c[j][3], ph, pl);
            Ph[r_hi * PST2 + 4 * j + gc] = ph;
            Pl[r_hi * PST2 + 4 * j + gc] = pl;
        }
        __syncwarp();
        // P @ V
#pragma unroll
        for (int ks = 0; ks < 4; ks++) {
            int cb = ks * 8;
            uint32_t ah0 = Ph[r_lo * PST2 + cb + gc], ah1 = Ph[r_hi * PST2 + cb + gc];
            uint32_t ah2 = Ph[r_lo * PST2 + cb + gc + 4], ah3 = Ph[r_hi * PST2 + cb + gc + 4];
            uint32_t al0 = Pl[r_lo * PST2 + cb + gc], al1 = Pl[r_hi * PST2 + cb + gc];
            uint32_t al2 = Pl[r_lo * PST2 + cb + gc + 4], al3 = Pl[r_hi * PST2 + cb + gc + 4];
#pragma unroll
            for (int nb = 0; nb < 16; nb++) {
                uint32_t bh0 = Vh[(nb * 8 + gr) * VST2 + cb + gc];
                uint32_t bh1 = Vh[(nb * 8 + gr) * VST2 + cb + gc + 4];
                uint32_t bl0 = Vl[(nb * 8 + gr) * VST2 + cb + gc];
                uint32_t bl1 = Vl[(nb * 8 + gr) * VST2 + cb + gc + 4];
                MMAH(o[nb], ah0, ah1, ah2, ah3, bh0, bh1);
                MMAH(o[nb], ah0, ah1, ah2, ah3, bl0, bl1);
                MMAH(o[nb], al0, al1, al2, al3, bh0, bh1);
            }
        }
    }
    float inv_lo = 1.f / l_lo, inv_hi = 1.f / l_hi;
    float* d_lo = g_ctx + ((size_t)(b * SEQ + q0 + r_lo)) * HID + h * HD;
    float* d_hi = g_ctx + ((size_t)(b * SEQ + q0 + r_hi)) * HID + h * HD;
#pragma unroll
    for (int nb = 0; nb < 16; nb++) {
        *(float2*)&d_lo[nb * 8 + 2 * gc] = make_float2(o[nb][0] * inv_lo, o[nb][1] * inv_lo);
        *(float2*)&d_hi[nb * 8 + 2 * gc] = make_float2(o[nb][2] * inv_hi, o[nb][3] * inv_hi);
    }
}

extern "C" void kernel_launch(void* const* d_in, const int* in_sizes, int n_in,
                              void* d_out, int out_size) {
    const float* x = (const float*)d_in[0];
    const float* wq = (const float*)d_in[1];
    const float* wk = (const float*)d_in[2];
    const float* wv = (const float*)d_in[3];
    const float* wo = (const float*)d_in[4];
    float* out = (float*)d_out;
    cudaFuncSetAttribute(k_attn, cudaFuncAttributeMaxDynamicSharedMemorySize, ATTN_SMEM);
    k_tab<<<256, 512>>>();
    k_wabs_partial<<<dim3(64, 4), 256>>>(wq, wk, wv, wo);
    k_wabs_final<<<4, 64>>>();
    k_quant_w<<<dim3(HID * HID / 1024, 4), 256>>>(wq, wk, wv, wo);
    k_quant_act<<<TOK, 256>>>(x, 0);
    k_gemm<<<dim3(16, 32), 256>>>(0, out);
    k_gemm<<<dim3(16, 32), 256>>>(1, out);
    k_gemm<<<dim3(16, 32), 256>>>(2, out);
    k_rope<<<TOK, 256>>>();
    k_vt<<<dim3(SEQ / 32, HD / 32, NH * 2), dim3(32, 8)>>>();
    k_attn<<<dim3(NH, 2, SEQ / 128), 256, ATTN_SMEM>>>();
    k_quant_act<<<TOK, 256>>>(nullptr, 1);
    k_gemm<<<dim3(16, 32), 256>>>(3, out);
}

// round 10
// speedup vs baseline: 2.0856x; 1.1722x over previous
#include <cuda_runtime.h>
#include <cuda_bf16.h>
#include <cuda_fp16.h>
#include <math.h>
#include <stdint.h>

#define HID 2048
#define TOK 4096
#define NH 16
#define HD 128
#define SEQ 2048
#define QBF 127.0f

__device__ int8_t g_w8[4][HID * HID];
__device__ float g_s[4];
__device__ float g_part[4 * 64];
__device__ int8_t g_x8[TOK * HID];
__device__ float g_xg[TOK];
__device__ float g_q[TOK * HID];
__device__ float g_k[TOK * HID];
__device__ float g_v[TOK * HID];
__device__ float g_qr[TOK * HID];
__device__ float g_kr[TOK * HID];
__device__ float g_vt[TOK * HID];
__device__ float g_ctx[TOK * HID];
__device__ int8_t g_c8[TOK * HID];
__device__ float g_cg[TOK];
__device__ float g_tc[SEQ * 64];
__device__ float g_ts[SEQ * 64];

__device__ __forceinline__ uint32_t sptr(const void* p) {
    return (uint32_t)__cvta_generic_to_shared(p);
}

#define CP16(s, g) asm volatile("cp.async.ca.shared.global [%0], [%1], 16;\n" ::"r"(s), "l"(g))
#define CPC asm volatile("cp.async.commit_group;\n")
#define CPW(n) asm volatile("cp.async.wait_group %0;\n" ::"n"(n))
#define LDSM4(r0, r1, r2, r3, a)                                                        \
    asm volatile("ldmatrix.sync.aligned.m8n8.x4.shared.b16 {%0,%1,%2,%3}, [%4];\n"      \
                 : "=r"(r0), "=r"(r1), "=r"(r2), "=r"(r3) : "r"(a))
#define MMAI(d, a, b)                                                                   \
    asm volatile("mma.sync.aligned.m16n8k32.row.col.s32.s8.s8.s32 "                     \
                 "{%0,%1,%2,%3},{%4,%5,%6,%7},{%8,%9},{%0,%1,%2,%3};\n"                 \
                 : "+r"(d[0]), "+r"(d[1]), "+r"(d[2]), "+r"(d[3])                       \
                 : "r"(a[0]), "r"(a[1]), "r"(a[2]), "r"(a[3]), "r"(b[0]), "r"(b[1]))
#define MMAH(d, a0, a1, a2, a3, b0, b1)                                                 \
    asm volatile("mma.sync.aligned.m16n8k16.row.col.f32.f16.f16.f32 "                   \
                 "{%0,%1,%2,%3},{%4,%5,%6,%7},{%8,%9},{%0,%1,%2,%3};\n"                 \
                 : "+f"(d[0]), "+f"(d[1]), "+f"(d[2]), "+f"(d[3])                       \
                 : "r"(a0), "r"(a1), "r"(a2), "r"(a3), "r"(b0), "r"(b1))

__device__ __forceinline__ void h2split(float x, float y, uint32_t& hi, uint32_t& lo) {
    __half2 h = __floats2half2_rn(x, y);
    float2 hf = __half22float2(h);
    __half2 l = __floats2half2_rn(x - hf.x, y - hf.y);
    hi = *(uint32_t*)&h;
    lo = *(uint32_t*)&l;
}

__global__ __launch_bounds__(512) void k_tab() {
    int i = blockIdx.x * 512 + threadIdx.x;
    int s = i >> 6, dp = i & 63;
    float ff = (float)pow(10000.0, -(double)dp / 64.0);
    float angf = (float)s * ff;
    double ang = fmod((double)angf, 6.283185307179586476925287);
    g_tc[i] = (float)cos(ang);
    g_ts[i] = (float)sin(ang);
}

__global__ __launch_bounds__(256) void k_wabs_partial(const float* __restrict__ w0,
        const float* __restrict__ w1, const float* __restrict__ w2, const float* __restrict__ w3) {
    const float* w = (blockIdx.y == 0) ? w0 : (blockIdx.y == 1) ? w1 : (blockIdx.y == 2) ? w2 : w3;
    const float4* w4 = (const float4*)(w + (size_t)blockIdx.x * 65536);
    float s = 0.f;
    for (int i = threadIdx.x; i < 16384; i += 256) {
        float4 v = w4[i];
        s += fabsf(v.x) + fabsf(v.y) + fabsf(v.z) + fabsf(v.w);
    }
    __shared__ float red[256];
    red[threadIdx.x] = s;
    __syncthreads();
    for (int st = 128; st > 0; st >>= 1) {
        if (threadIdx.x < st) red[threadIdx.x] += red[threadIdx.x + st];
        __syncthreads();
    }
    if (threadIdx.x == 0) g_part[blockIdx.y * 64 + blockIdx.x] = red[0];
}

__global__ __launch_bounds__(64) void k_wabs_final() {
    __shared__ float red[64];
    red[threadIdx.x] = g_part[blockIdx.x * 64 + threadIdx.x];
    __syncthreads();
    for (int st = 32; st > 0; st >>= 1) {
        if (threadIdx.x < st) red[threadIdx.x] += red[threadIdx.x + st];
        __syncthreads();
    }
    if (threadIdx.x == 0) g_s[blockIdx.x] = red[0] / (float)(HID * HID) + 1e-5f;
}

__global__ __launch_bounds__(256) void k_quant_w(const float* __restrict__ w0,
        const float* __restrict__ w1, const float* __restrict__ w2, const float* __restrict__ w3) {
    int m = blockIdx.y;
    const float* w = (m == 0) ? w0 : (m == 1) ? w1 : (m == 2) ? w2 : w3;
    float s = g_s[m];
    int idx = (blockIdx.x * 256 + threadIdx.x) * 4;
    float4 v = *(const float4*)(w + idx);
    float qx = fminf(1.f, fmaxf(-1.f, rintf(v.x / s)));
    float qy = fminf(1.f, fmaxf(-1.f, rintf(v.y / s)));
    float qz = fminf(1.f, fmaxf(-1.f, rintf(v.z / s)));
    float qw = fminf(1.f, fmaxf(-1.f, rintf(v.w / s)));
    char4 pk = make_char4((char)(int)qx, (char)(int)qy, (char)(int)qz, (char)(int)qw);
    *(char4*)&g_w8[m][idx] = pk;
}

__global__ __launch_bounds__(256) void k_quant_act(const float* __restrict__ ext, int use_ctx) {
    int row = blockIdx.x;
    const float* src = use_ctx ? g_ctx : ext;
    int8_t* dst = use_ctx ? g_c8 : g_x8;
    float* gout = use_ctx ? g_cg : g_xg;
    const float4* xr = (const float4*)(src + (size_t)row * HID);
    float4 v0 = xr[threadIdx.x];
    float4 v1 = xr[threadIdx.x + 256];
    float mx = fmaxf(fmaxf(fabsf(v0.x), fabsf(v0.y)), fmaxf(fabsf(v0.z), fabsf(v0.w)));
    mx = fmaxf(mx, fmaxf(fmaxf(fabsf(v1.x), fabsf(v1.y)), fmaxf(fabsf(v1.z), fabsf(v1.w))));
    __shared__ float red[256];
    red[threadIdx.x] = mx;
    __syncthreads();
    for (int st = 128; st > 0; st >>= 1) {
        if (threadIdx.x < st) red[threadIdx.x] = fmaxf(red[threadIdx.x], red[threadIdx.x + st]);
        __syncthreads();
    }
    float g = red[0] + 1e-5f;
    if (threadIdx.x == 0) gout[row] = g;
    float t = QBF / g;
    int8_t* orow = dst + (size_t)row * HID;
    float4 vv[2] = {v0, v1};
    int offs[2] = {(int)threadIdx.x * 4, ((int)threadIdx.x + 256) * 4};
#pragma unroll
    for (int hh = 0; hh < 2; ++hh) {
        float a = fminf(QBF, fmaxf(-QBF, rintf(vv[hh].x * t)));
        float b = fminf(QBF, fmaxf(-QBF, rintf(vv[hh].y * t)));
        float c = fminf(QBF, fmaxf(-QBF, rintf(vv[hh].z * t)));
        float d = fminf(QBF, fmaxf(-QBF, rintf(vv[hh].w * t)));
        char4 pk = make_char4((char)(int)a, (char)(int)b, (char)(int)c, (char)(int)d);
        *(char4*)&orow[offs[hh]] = pk;
    }
}

// ---- INT8 MMA GEMM: C[m][n] = (sum_k A[m,k]*W[n,k]) * g[m]*s/127 ----
// s8 m16n8k32, exact s32 accumulation. Tile 128x128, BK=64 bytes, row stride 80.
__global__ __launch_bounds__(256) void k_gemm(int mat, float* __restrict__ dout) {
    __shared__ int8_t As[2][128 * 80];
    __shared__ int8_t Bs[2][128 * 80];
    const int8_t* A = (mat == 3) ? g_c8 : g_x8;
    const float* gv = (mat == 3) ? g_cg : g_xg;
    const int8_t* W = g_w8[mat];
    float* C = (mat == 0) ? g_q : (mat == 1) ? g_k : (mat == 2) ? g_v : dout;
    int tid = threadIdx.x;
    int bm = blockIdx.y * 128, bn = blockIdx.x * 128;
    int warp = tid >> 5, lane = tid & 31;
    int wm = (warp >> 2) * 64, wn = (warp & 3) * 32;
    int acc[4][4][4];
#pragma unroll
    for (int i = 0; i < 4; i++)
#pragma unroll
        for (int j = 0; j < 4; j++)
#pragma unroll
            for (int r = 0; r < 4; r++) acc[i][j][r] = 0;
    const int8_t* Ab = A + (size_t)bm * HID;
    const int8_t* Wb = W + (size_t)bn * HID;
#define GLOAD(bf, k0)                                                              \
    for (int c = tid; c < 512; c += 256) {                                         \
        int rr = c >> 2, kc = (c & 3) << 4;                                        \
        CP16(sptr(&As[bf][rr * 80 + kc]), Ab + (size_t)rr * HID + (k0) + kc);      \
        CP16(sptr(&Bs[bf][rr * 80 + kc]), Wb + (size_t)rr * HID + (k0) + kc);      \
    }
    GLOAD(0, 0);
    CPC;
    for (int kt = 0; kt < 32; kt++) {
        int buf = kt & 1;
        if (kt < 31) {
            GLOAD(buf ^ 1, (kt + 1) * 64);
            CPC;
            CPW(1);
        } else {
            CPW(0);
        }
        __syncthreads();
#pragma unroll
        for (int ks = 0; ks < 2; ks++) {
            uint32_t a[4][4], b[4][2];
#pragma unroll
            for (int am = 0; am < 4; am++) {
                uint32_t ad = sptr(&As[buf][(wm + am * 16 + (lane & 15)) * 80 + ks * 32 + ((lane >> 4) << 4)]);
                LDSM4(a[am][0], a[am][1], a[am][2], a[am][3], ad);
            }
#pragma unroll
            for (int bp = 0; bp < 2; bp++) {
                int g = lane >> 3;
                int nr = wn + bp * 16 + (lane & 7) + ((g >> 1) << 3);
                int kc = ks * 32 + ((g & 1) << 4);
                uint32_t ad = sptr(&Bs[buf][nr * 80 + kc]);
                uint32_t r0, r1, r2, r3;
                LDSM4(r0, r1, r2, r3, ad);
                b[2 * bp][0] = r0; b[2 * bp][1] = r1;
                b[2 * bp + 1][0] = r2; b[2 * bp + 1][1] = r3;
            }
#pragma unroll
            for (int am = 0; am < 4; am++)
#pragma unroll
                for (int bf = 0; bf < 4; bf++) MMAI(acc[am][bf], a[am], b[bf]);
        }
        __syncthreads();
    }
    float sw = g_s[mat] * (1.0f / QBF);
#pragma unroll
    for (int am = 0; am < 4; am++) {
        int r0 = bm + wm + am * 16 + (lane >> 2);
        float s0 = gv[r0] * sw, s1 = gv[r0 + 8] * sw;
#pragma unroll
        for (int bf = 0; bf < 4; bf++) {
            int cc = bn + wn + bf * 8 + ((lane & 3) << 1);
            float* p0 = C + (size_t)r0 * HID + cc;
            p0[0] = (float)acc[am][bf][0] * s0;
            p0[1] = (float)acc[am][bf][1] * s0;
            float* p1 = p0 + (size_t)8 * HID;
            p1[0] = (float)acc[am][bf][2] * s1;
            p1[1] = (float)acc[am][bf][3] * s1;
        }
    }
}

__global__ __launch_bounds__(256) void k_rope() {
    int tok = blockIdx.x;
    int s = tok & (SEQ - 1);
    size_t tb = (size_t)tok * HID;
    for (int idx = threadIdx.x; idx < HID; idx += 256) {
        int d = idx & 127;
        int dp = d & 63;
        int partner = (idx & ~127) | ((d + 64) & 127);
        float c = g_tc[s * 64 + dp];
        float sn = g_ts[s * 64 + dp];
        float sgn = (d < 64) ? -sn : sn;
        g_qr[tb + idx] = g_q[tb + idx] * c + g_q[tb + partner] * sgn;
        g_kr[tb + idx] = g_k[tb + idx] * c + g_k[tb + partner] * sgn;
    }
}

__global__ __launch_bounds__(256) void k_vt() {
    __shared__ float t[32][33];
    int s0 = blockIdx.x * 32, d0 = blockIdx.y * 32;
    int h = blockIdx.z & (NH - 1), b = blockIdx.z >> 4;
    int tx = threadIdx.x, ty = threadIdx.y;
#pragma unroll
    for (int i = 0; i < 4; i++) {
        int s = s0 + ty + 8 * i;
        t[ty + 8 * i][tx] = g_v[((size_t)(b * SEQ + s)) * HID + h * HD + d0 + tx];
    }
    __syncthreads();
#pragma unroll
    for (int i = 0; i < 4; i++) {
        int d = d0 + ty + 8 * i;
        g_vt[((size_t)((b * NH + h) * HD + d)) * SEQ + s0 + tx] = t[tx][ty + 8 * i];
    }
}

// flash attention: fp16 2-term split (hi+lo), m16n8k16 MMAs (unchanged, passing)
#define QST2 68
#define KST2 68
#define VST2 36
#define PST2 36
#define ATTN_SMEM ((2 * 128 * QST2 + 2 * 64 * KST2 + 2 * 128 * VST2 + 2 * 128 * PST2) * 4)
__global__ __launch_bounds__(256) void k_attn() {
    extern __shared__ uint32_t smu[];
    uint32_t* Qh = smu;
    uint32_t* Ql = Qh + 128 * QST2;
    uint32_t* Kh = Ql + 128 * QST2;
    uint32_t* Kl = Kh + 64 * KST2;
    uint32_t* Vh = Kl + 64 * KST2;
    uint32_t* Vl = Vh + 128 * VST2;
    uint32_t* Ph = Vl + 128 * VST2;
    uint32_t* Pl = Ph + 128 * PST2;
    int h = blockIdx.x, b = blockIdx.y, q0 = blockIdx.z * 128;
    int tid = threadIdx.x, w = tid >> 5, lane = tid & 31;
    int gr = lane >> 2, gc = lane & 3;
    const float scale = 0.08838834764831845f;
    size_t qb = ((size_t)(b * SEQ + q0)) * HID + h * HD;
    for (int e = tid; e < 128 * 32; e += 256) {
        int r = e >> 5, cg = e & 31;
        float4 v = *(const float4*)(g_qr + qb + (size_t)r * HID + cg * 4);
        uint32_t h0, l0, h1, l1;
        h2split(v.x, v.y, h0, l0);
        h2split(v.z, v.w, h1, l1);
        *(uint2*)&Qh[r * QST2 + 2 * cg] = make_uint2(h0, h1);
        *(uint2*)&Ql[r * QST2 + 2 * cg] = make_uint2(l0, l1);
    }
    float o[16][4];
#pragma unroll
    for (int i = 0; i < 16; i++) { o[i][0] = o[i][1] = o[i][2] = o[i][3] = 0.f; }
    float m_lo = -1e30f, m_hi = -1e30f, l_lo = 0.f, l_hi = 0.f;
    int wr = w * 16;
    const int r_lo = wr + gr, r_hi = wr + gr + 8;
    size_t vtb = ((size_t)((b * NH + h) * HD)) * SEQ;
    for (int kt = 0; kt < SEQ / 64; kt++) {
        __syncthreads();
        size_t kb0 = ((size_t)(b * SEQ + kt * 64)) * HID + h * HD;
        for (int e = tid; e < 64 * 32; e += 256) {
            int r = e >> 5, cg = e & 31;
            float4 v = *(const float4*)(g_kr + kb0 + (size_t)r * HID + cg * 4);
            uint32_t h0, l0, h1, l1;
            h2split(v.x, v.y, h0, l0);
            h2split(v.z, v.w, h1, l1);
            *(uint2*)&Kh[r * KST2 + 2 * cg] = make_uint2(h0, h1);
            *(uint2*)&Kl[r * KST2 + 2 * cg] = make_uint2(l0, l1);
        }
        for (int e = tid; e < 128 * 16; e += 256) {
            int d = e >> 4, kg = e & 15;
            float4 v = *(const float4*)(g_vt + vtb + (size_t)d * SEQ + kt * 64 + kg * 4);
            uint32_t h0, l0, h1, l1;
            h2split(v.x, v.y, h0, l0);
            h2split(v.z, v.w, h1, l1);
            *(uint2*)&Vh[d * VST2 + 2 * kg] = make_uint2(h0, h1);
            *(uint2*)&Vl[d * VST2 + 2 * kg] = make_uint2(l0, l1);
        }
        __syncthreads();
        float c[8][4];
#pragma unroll
        for (int j = 0; j < 8; j++) { c[j][0] = c[j][1] = c[j][2] = c[j][3] = 0.f; }
#pragma unroll
        for (int ks = 0; ks < 8; ks++) {
            int cb = ks * 8;
            uint32_t ah0 = Qh[r_lo * QST2 + cb + gc], ah1 = Qh[r_hi * QST2 + cb + gc];
            uint32_t ah2 = Qh[r_lo * QST2 + cb + gc + 4], ah3 = Qh[r_hi * QST2 + cb + gc + 4];
            uint32_t al0 = Ql[r_lo * QST2 + cb + gc], al1 = Ql[r_hi * QST2 + cb + gc];
            uint32_t al2 = Ql[r_lo * QST2 + cb + gc + 4], al3 = Ql[r_hi * QST2 + cb + gc + 4];
#pragma unroll
            for (int nb = 0; nb < 8; nb++) {
                uint32_t bh0 = Kh[(nb * 8 + gr) * KST2 + cb + gc];
                uint32_t bh1 = Kh[(nb * 8 + gr) * KST2 + cb + gc + 4];
                uint32_t bl0 = Kl[(nb * 8 + gr) * KST2 + cb + gc];
                uint32_t bl1 = Kl[(nb * 8 + gr) * KST2 + cb + gc + 4];
                MMAH(c[nb], ah0, ah1, ah2, ah3, bh0, bh1);
                MMAH(c[nb], ah0, ah1, ah2, ah3, bl0, bl1);
                MMAH(c[nb], al0, al1, al2, al3, bh0, bh1);
            }
        }
        float mx_lo = -1e30f, mx_hi = -1e30f;
#pragma unroll
        for (int j = 0; j < 8; j++) {
            mx_lo = fmaxf(mx_lo, fmaxf(c[j][0], c[j][1]));
            mx_hi = fmaxf(mx_hi, fmaxf(c[j][2], c[j][3]));
        }
        mx_lo = fmaxf(mx_lo, __shfl_xor_sync(0xffffffffu, mx_lo, 1));
        mx_lo = fmaxf(mx_lo, __shfl_xor_sync(0xffffffffu, mx_lo, 2));
        mx_hi = fmaxf(mx_hi, __shfl_xor_sync(0xffffffffu, mx_hi, 1));
        mx_hi = fmaxf(mx_hi, __shfl_xor_sync(0xffffffffu, mx_hi, 2));
        float mn_lo = fmaxf(m_lo, mx_lo * scale);
        float mn_hi = fmaxf(m_hi, mx_hi * scale);
        float ts_lo = 0.f, ts_hi = 0.f;
#pragma unroll
        for (int j = 0; j < 8; j++) {
            c[j][0] = __expf(fmaf(c[j][0], scale, -mn_lo));
            c[j][1] = __expf(fmaf(c[j][1], scale, -mn_lo));
            c[j][2] = __expf(fmaf(c[j][2], scale, -mn_hi));
            c[j][3] = __expf(fmaf(c[j][3], scale, -mn_hi));
            ts_lo += c[j][0] + c[j][1];
            ts_hi += c[j][2] + c[j][3];
        }
        ts_lo += __shfl_xor_sync(0xffffffffu, ts_lo, 1);
        ts_lo += __shfl_xor_sync(0xffffffffu, ts_lo, 2);
        ts_hi += __shfl_xor_sync(0xffffffffu, ts_hi, 1);
        ts_hi += __shfl_xor_sync(0xffffffffu, ts_hi, 2);
        float co_lo = __expf(m_lo - mn_lo), co_hi = __expf(m_hi - mn_hi);
        m_lo = mn_lo; m_hi = mn_hi;
        l_lo = l_lo * co_lo + ts_lo;
        l_hi = l_hi * co_hi + ts_hi;
#pragma unroll
        for (int j = 0; j < 16; j++) {
            o[j][0] *= co_lo; o[j][1] *= co_lo;
            o[j][2] *= co_hi; o[j][3] *= co_hi;
        }
#pragma unroll
        for (int j = 0; j < 8; j++) {
            uint32_t ph, pl;
            h2split(c[j][0], c[j][1], ph, pl);
            Ph[r_lo * PST2 + 4 * j + gc] = ph;
            Pl[r_lo * PST2 + 4 * j + gc] = pl;
            h2split(c[j][2], c[j][3], ph, pl);
            Ph[r_hi * PST2 + 4 * j + gc] = ph;
            Pl[r_hi * PST2 + 4 * j + gc] = pl;
        }
        __syncwarp();
#pragma unroll
        for (int ks = 0; ks < 4; ks++) {
            int cb = ks * 8;
            uint32_t ah0 = Ph[r_lo * PST2 + cb + gc], ah1 = Ph[r_hi * PST2 + cb + gc];
            uint32_t ah2 = Ph[r_lo * PST2 + cb + gc + 4], ah3 = Ph[r_hi * PST2 + cb + gc + 4];
            uint32_t al0 = Pl[r_lo * PST2 + cb + gc], al1 = Pl[r_hi * PST2 + cb + gc];
            uint32_t al2 = Pl[r_lo * PST2 + cb + gc + 4], al3 = Pl[r_hi * PST2 + cb + gc + 4];
#pragma unroll
            for (int nb = 0; nb < 16; nb++) {
                uint32_t bh0 = Vh[(nb * 8 + gr) * VST2 + cb + gc];
                uint32_t bh1 = Vh[(nb * 8 + gr) * VST2 + cb + gc + 4];
                uint32_t bl0 = Vl[(nb * 8 + gr) * VST2 + cb + gc];
                uint32_t bl1 = Vl[(nb * 8 + gr) * VST2 + cb + gc + 4];
                MMAH(o[nb], ah0, ah1, ah2, ah3, bh0, bh1);
                MMAH(o[nb], ah0, ah1, ah2, ah3, bl0, bl1);
                MMAH(o[nb], al0, al1, al2, al3, bh0, bh1);
            }
        }
    }
    float inv_lo = 1.f / l_lo, inv_hi = 1.f / l_hi;
    float* d_lo = g_ctx + ((size_t)(b * SEQ + q0 + r_lo)) * HID + h * HD;
    float* d_hi = g_ctx + ((size_t)(b * SEQ + q0 + r_hi)) * HID + h * HD;
#pragma unroll
    for (int nb = 0; nb < 16; nb++) {
        *(float2*)&d_lo[nb * 8 + 2 * gc] = make_float2(o[nb][0] * inv_lo, o[nb][1] * inv_lo);
        *(float2*)&d_hi[nb * 8 + 2 * gc] = make_float2(o[nb][2] * inv_hi, o[nb][3] * inv_hi);
    }
}

extern "C" void kernel_launch(void* const* d_in, const int* in_sizes, int n_in,
                              void* d_out, int out_size) {
    const float* x = (const float*)d_in[0];
    const float* wq = (const float*)d_in[1];
    const float* wk = (const float*)d_in[2];
    const float* wv = (const float*)d_in[3];
    const float* wo = (const float*)d_in[4];
    float* out = (float*)d_out;
    cudaFuncSetAttribute(k_attn, cudaFuncAttributeMaxDynamicSharedMemorySize, ATTN_SMEM);
    k_tab<<<256, 512>>>();
    k_wabs_partial<<<dim3(64, 4), 256>>>(wq, wk, wv, wo);
    k_wabs_final<<<4, 64>>>();
    k_quant_w<<<dim3(HID * HID / 1024, 4), 256>>>(wq, wk, wv, wo);
    k_quant_act<<<TOK, 256>>>(x, 0);
    k_gemm<<<dim3(16, 32), 256>>>(0, out);
    k_gemm<<<dim3(16, 32), 256>>>(1, out);
    k_gemm<<<dim3(16, 32), 256>>>(2, out);
    k_rope<<<TOK, 256>>>();
    k_vt<<<dim3(SEQ / 32, HD / 32, NH * 2), dim3(32, 8)>>>();
    k_attn<<<dim3(NH, 2, SEQ / 128), 256, ATTN_SMEM>>>();
    k_quant_act<<<TOK, 256>>>(nullptr, 1);
    k_gemm<<<dim3(16, 32), 256>>>(3, out);
}

// round 11
// speedup vs baseline: 2.5089x; 1.2030x over previous
#include <cuda_runtime.h>
#include <cuda_bf16.h>
#include <cuda_fp16.h>
#include <math.h>
#include <stdint.h>

#define HID 2048
#define TOK 4096
#define NH 16
#define HD 128
#define SEQ 2048
#define QBF 127.0f

__device__ int8_t g_w8[4][HID * HID];
__device__ float g_s[4];
__device__ float g_part[4 * 64];
__device__ int8_t g_x8[TOK * HID];
__device__ float g_xg[TOK];
__device__ float g_q[TOK * HID];
__device__ float g_k[TOK * HID];
__device__ float g_v[TOK * HID];
__device__ float g_ctx[TOK * HID];
__device__ int8_t g_c8[TOK * HID];
__device__ float g_cg[TOK];
__device__ float g_tc[SEQ * 64];
__device__ float g_ts[SEQ * 64];
// pre-split packed half2 (hi/lo) operands for attention
__device__ uint32_t g_qh[TOK * HID / 2];
__device__ uint32_t g_ql[TOK * HID / 2];
__device__ uint32_t g_kh[TOK * HID / 2];
__device__ uint32_t g_kl[TOK * HID / 2];
__device__ uint32_t g_vth[TOK * HID / 2];
__device__ uint32_t g_vtl[TOK * HID / 2];

__device__ __forceinline__ uint32_t sptr(const void* p) {
    return (uint32_t)__cvta_generic_to_shared(p);
}

#define CP16(s, g) asm volatile("cp.async.ca.shared.global [%0], [%1], 16;\n" ::"r"(s), "l"(g))
#define CPC asm volatile("cp.async.commit_group;\n")
#define CPW(n) asm volatile("cp.async.wait_group %0;\n" ::"n"(n))
#define LDSM4(r0, r1, r2, r3, a)                                                        \
    asm volatile("ldmatrix.sync.aligned.m8n8.x4.shared.b16 {%0,%1,%2,%3}, [%4];\n"      \
                 : "=r"(r0), "=r"(r1), "=r"(r2), "=r"(r3) : "r"(a))
#define MMAI(d, a, b)                                                                   \
    asm volatile("mma.sync.aligned.m16n8k32.row.col.s32.s8.s8.s32 "                     \
                 "{%0,%1,%2,%3},{%4,%5,%6,%7},{%8,%9},{%0,%1,%2,%3};\n"                 \
                 : "+r"(d[0]), "+r"(d[1]), "+r"(d[2]), "+r"(d[3])                       \
                 : "r"(a[0]), "r"(a[1]), "r"(a[2]), "r"(a[3]), "r"(b[0]), "r"(b[1]))
#define MMAH(d, a0, a1, a2, a3, b0, b1)                                                 \
    asm volatile("mma.sync.aligned.m16n8k16.row.col.f32.f16.f16.f32 "                   \
                 "{%0,%1,%2,%3},{%4,%5,%6,%7},{%8,%9},{%0,%1,%2,%3};\n"                 \
                 : "+f"(d[0]), "+f"(d[1]), "+f"(d[2]), "+f"(d[3])                       \
                 : "r"(a0), "r"(a1), "r"(a2), "r"(a3), "r"(b0), "r"(b1))

__device__ __forceinline__ void h2split(float x, float y, uint32_t& hi, uint32_t& lo) {
    __half2 h = __floats2half2_rn(x, y);
    float2 hf = __half22float2(h);
    __half2 l = __floats2half2_rn(x - hf.x, y - hf.y);
    hi = *(uint32_t*)&h;
    lo = *(uint32_t*)&l;
}

__global__ __launch_bounds__(512) void k_tab() {
    int i = blockIdx.x * 512 + threadIdx.x;
    int s = i >> 6, dp = i & 63;
    float ff = (float)pow(10000.0, -(double)dp / 64.0);
    float angf = (float)s * ff;
    double ang = fmod((double)angf, 6.283185307179586476925287);
    g_tc[i] = (float)cos(ang);
    g_ts[i] = (float)sin(ang);
}

__global__ __launch_bounds__(256) void k_wabs_partial(const float* __restrict__ w0,
        const float* __restrict__ w1, const float* __restrict__ w2, const float* __restrict__ w3) {
    const float* w = (blockIdx.y == 0) ? w0 : (blockIdx.y == 1) ? w1 : (blockIdx.y == 2) ? w2 : w3;
    const float4* w4 = (const float4*)(w + (size_t)blockIdx.x * 65536);
    float s = 0.f;
    for (int i = threadIdx.x; i < 16384; i += 256) {
        float4 v = w4[i];
        s += fabsf(v.x) + fabsf(v.y) + fabsf(v.z) + fabsf(v.w);
    }
    __shared__ float red[256];
    red[threadIdx.x] = s;
    __syncthreads();
    for (int st = 128; st > 0; st >>= 1) {
        if (threadIdx.x < st) red[threadIdx.x] += red[threadIdx.x + st];
        __syncthreads();
    }
    if (threadIdx.x == 0) g_part[blockIdx.y * 64 + blockIdx.x] = red[0];
}

__global__ __launch_bounds__(64) void k_wabs_final() {
    __shared__ float red[64];
    red[threadIdx.x] = g_part[blockIdx.x * 64 + threadIdx.x];
    __syncthreads();
    for (int st = 32; st > 0; st >>= 1) {
        if (threadIdx.x < st) red[threadIdx.x] += red[threadIdx.x + st];
        __syncthreads();
    }
    if (threadIdx.x == 0) g_s[blockIdx.x] = red[0] / (float)(HID * HID) + 1e-5f;
}

__global__ __launch_bounds__(256) void k_quant_w(const float* __restrict__ w0,
        const float* __restrict__ w1, const float* __restrict__ w2, const float* __restrict__ w3) {
    int m = blockIdx.y;
    const float* w = (m == 0) ? w0 : (m == 1) ? w1 : (m == 2) ? w2 : w3;
    float s = g_s[m];
    int idx = (blockIdx.x * 256 + threadIdx.x) * 4;
    float4 v = *(const float4*)(w + idx);
    float qx = fminf(1.f, fmaxf(-1.f, rintf(v.x / s)));
    float qy = fminf(1.f, fmaxf(-1.f, rintf(v.y / s)));
    float qz = fminf(1.f, fmaxf(-1.f, rintf(v.z / s)));
    float qw = fminf(1.f, fmaxf(-1.f, rintf(v.w / s)));
    char4 pk = make_char4((char)(int)qx, (char)(int)qy, (char)(int)qz, (char)(int)qw);
    *(char4*)&g_w8[m][idx] = pk;
}

__global__ __launch_bounds__(256) void k_quant_act(const float* __restrict__ ext, int use_ctx) {
    int row = blockIdx.x;
    const float* src = use_ctx ? g_ctx : ext;
    int8_t* dst = use_ctx ? g_c8 : g_x8;
    float* gout = use_ctx ? g_cg : g_xg;
    const float4* xr = (const float4*)(src + (size_t)row * HID);
    float4 v0 = xr[threadIdx.x];
    float4 v1 = xr[threadIdx.x + 256];
    float mx = fmaxf(fmaxf(fabsf(v0.x), fabsf(v0.y)), fmaxf(fabsf(v0.z), fabsf(v0.w)));
    mx = fmaxf(mx, fmaxf(fmaxf(fabsf(v1.x), fabsf(v1.y)), fmaxf(fabsf(v1.z), fabsf(v1.w))));
    __shared__ float red[256];
    red[threadIdx.x] = mx;
    __syncthreads();
    for (int st = 128; st > 0; st >>= 1) {
        if (threadIdx.x < st) red[threadIdx.x] = fmaxf(red[threadIdx.x], red[threadIdx.x + st]);
        __syncthreads();
    }
    float g = red[0] + 1e-5f;
    if (threadIdx.x == 0) gout[row] = g;
    float t = QBF / g;
    int8_t* orow = dst + (size_t)row * HID;
    float4 vv[2] = {v0, v1};
    int offs[2] = {(int)threadIdx.x * 4, ((int)threadIdx.x + 256) * 4};
#pragma unroll
    for (int hh = 0; hh < 2; ++hh) {
        float a = fminf(QBF, fmaxf(-QBF, rintf(vv[hh].x * t)));
        float b = fminf(QBF, fmaxf(-QBF, rintf(vv[hh].y * t)));
        float c = fminf(QBF, fmaxf(-QBF, rintf(vv[hh].z * t)));
        float d = fminf(QBF, fmaxf(-QBF, rintf(vv[hh].w * t)));
        char4 pk = make_char4((char)(int)a, (char)(int)b, (char)(int)c, (char)(int)d);
        *(char4*)&orow[offs[hh]] = pk;
    }
}

// ---- INT8 MMA GEMM (unchanged, passing) ----
__global__ __launch_bounds__(256) void k_gemm(int mat, float* __restrict__ dout) {
    __shared__ int8_t As[2][128 * 80];
    __shared__ int8_t Bs[2][128 * 80];
    const int8_t* A = (mat == 3) ? g_c8 : g_x8;
    const float* gv = (mat == 3) ? g_cg : g_xg;
    const int8_t* W = g_w8[mat];
    float* C = (mat == 0) ? g_q : (mat == 1) ? g_k : (mat == 2) ? g_v : dout;
    int tid = threadIdx.x;
    int bm = blockIdx.y * 128, bn = blockIdx.x * 128;
    int warp = tid >> 5, lane = tid & 31;
    int wm = (warp >> 2) * 64, wn = (warp & 3) * 32;
    int acc[4][4][4];
#pragma unroll
    for (int i = 0; i < 4; i++)
#pragma unroll
        for (int j = 0; j < 4; j++)
#pragma unroll
            for (int r = 0; r < 4; r++) acc[i][j][r] = 0;
    const int8_t* Ab = A + (size_t)bm * HID;
    const int8_t* Wb = W + (size_t)bn * HID;
#define GLOAD(bf, k0)                                                              \
    for (int c = tid; c < 512; c += 256) {                                         \
        int rr = c >> 2, kc = (c & 3) << 4;                                        \
        CP16(sptr(&As[bf][rr * 80 + kc]), Ab + (size_t)rr * HID + (k0) + kc);      \
        CP16(sptr(&Bs[bf][rr * 80 + kc]), Wb + (size_t)rr * HID + (k0) + kc);      \
    }
    GLOAD(0, 0);
    CPC;
    for (int kt = 0; kt < 32; kt++) {
        int buf = kt & 1;
        if (kt < 31) {
            GLOAD(buf ^ 1, (kt + 1) * 64);
            CPC;
            CPW(1);
        } else {
            CPW(0);
        }
        __syncthreads();
#pragma unroll
        for (int ks = 0; ks < 2; ks++) {
            uint32_t a[4][4], b[4][2];
#pragma unroll
            for (int am = 0; am < 4; am++) {
                uint32_t ad = sptr(&As[buf][(wm + am * 16 + (lane & 15)) * 80 + ks * 32 + ((lane >> 4) << 4)]);
                LDSM4(a[am][0], a[am][1], a[am][2], a[am][3], ad);
            }
#pragma unroll
            for (int bp = 0; bp < 2; bp++) {
                int g = lane >> 3;
                int nr = wn + bp * 16 + (lane & 7) + ((g >> 1) << 3);
                int kc = ks * 32 + ((g & 1) << 4);
                uint32_t ad = sptr(&Bs[buf][nr * 80 + kc]);
                uint32_t r0, r1, r2, r3;
                LDSM4(r0, r1, r2, r3, ad);
                b[2 * bp][0] = r0; b[2 * bp][1] = r1;
                b[2 * bp + 1][0] = r2; b[2 * bp + 1][1] = r3;
            }
#pragma unroll
            for (int am = 0; am < 4; am++)
#pragma unroll
                for (int bf = 0; bf < 4; bf++) MMAI(acc[am][bf], a[am], b[bf]);
        }
        __syncthreads();
    }
    float sw = g_s[mat] * (1.0f / QBF);
#pragma unroll
    for (int am = 0; am < 4; am++) {
        int r0 = bm + wm + am * 16 + (lane >> 2);
        float s0 = gv[r0] * sw, s1 = gv[r0 + 8] * sw;
#pragma unroll
        for (int bf = 0; bf < 4; bf++) {
            int cc = bn + wn + bf * 8 + ((lane & 3) << 1);
            float* p0 = C + (size_t)r0 * HID + cc;
            p0[0] = (float)acc[am][bf][0] * s0;
            p0[1] = (float)acc[am][bf][1] * s0;
            float* p1 = p0 + (size_t)8 * HID;
            p1[0] = (float)acc[am][bf][2] * s1;
            p1[1] = (float)acc[am][bf][3] * s1;
        }
    }
}

// RoPE + split: emit packed half2 hi/lo Q,K directly
__global__ __launch_bounds__(256) void k_rope() {
    int tok = blockIdx.x;
    int s = tok & (SEQ - 1);
    size_t tb = (size_t)tok * HID;
    for (int i = threadIdx.x; i < HID / 2; i += 256) {
        int d0 = 2 * i;
        float qv[2], kv[2];
#pragma unroll
        for (int u = 0; u < 2; u++) {
            int d = d0 + u;
            int dl = d & 127, dp = dl & 63;
            int partner = (d & ~127) | ((dl + 64) & 127);
            float c = g_tc[s * 64 + dp];
            float sn = g_ts[s * 64 + dp];
            float sgn = (dl < 64) ? -sn : sn;
            qv[u] = g_q[tb + d] * c + g_q[tb + partner] * sgn;
            kv[u] = g_k[tb + d] * c + g_k[tb + partner] * sgn;
        }
        uint32_t hh, ll;
        h2split(qv[0], qv[1], hh, ll);
        g_qh[tok * (HID / 2) + i] = hh;
        g_ql[tok * (HID / 2) + i] = ll;
        h2split(kv[0], kv[1], hh, ll);
        g_kh[tok * (HID / 2) + i] = hh;
        g_kl[tok * (HID / 2) + i] = ll;
    }
}

// V transpose + split: g_v [b,s][h,d] -> g_vth/g_vtl [(b*NH+h)*HD+d][s/2] (keys paired)
__global__ __launch_bounds__(256) void k_vt() {
    __shared__ float t[32][33];
    int s0 = blockIdx.x * 32, d0 = blockIdx.y * 32;
    int h = blockIdx.z & (NH - 1), b = blockIdx.z >> 4;
    int tx = threadIdx.x, ty = threadIdx.y;
    int tl = ty * 32 + tx;
#pragma unroll
    for (int i = 0; i < 4; i++) {
        int s = s0 + ty + 8 * i;
        t[ty + 8 * i][tx] = g_v[((size_t)(b * SEQ + s)) * HID + h * HD + d0 + tx];
    }
    __syncthreads();
    for (int e = tl; e < 512; e += 256) {
        int dl = e >> 4, p = e & 15;
        uint32_t hh, ll;
        h2split(t[2 * p][dl], t[2 * p + 1][dl], hh, ll);
        size_t ob = ((size_t)((b * NH + h) * HD + d0 + dl)) * (SEQ / 2) + s0 / 2 + p;
        g_vth[ob] = hh;
        g_vtl[ob] = ll;
    }
}

// flash attention: pre-split operands via cp.async; K single-buffer, V double-buffer.
#define QST2 68
#define KST2 68
#define VST2 36
#define PST2 36
#define ATTN_SMEM (53760 * 4)
__global__ __launch_bounds__(256) void k_attn() {
    extern __shared__ uint32_t smu[];
    uint32_t* Qh = smu;                    // 128*68
    uint32_t* Ql = smu + 8704;
    uint32_t* Kh = smu + 17408;            // 64*68
    uint32_t* Kl = smu + 21760;
    uint32_t* Vst = smu + 26112;           // 2 stages x (Vh 128*36 + Vl 128*36)
    uint32_t* Ph = smu + 44544;            // 128*36
    uint32_t* Pl = smu + 49152;
    int h = blockIdx.x, b = blockIdx.y, q0 = blockIdx.z * 128;
    int tid = threadIdx.x, w = tid >> 5, lane = tid & 31;
    int gr = lane >> 2, gc = lane & 3;
    const float scale = 0.08838834764831845f;
    const int HW = HID / 2;  // u32 per token row
    // prologue: Q + K(0) + V(0) via cp.async, one group
    for (int e = tid; e < 4096; e += 256) {
        int arr = e >> 11, r = (e & 2047) >> 4, c = e & 15;
        uint32_t* ds = arr ? Ql : Qh;
        const uint32_t* sr = (arr ? g_ql : g_qh) + (size_t)(b * SEQ + q0 + r) * HW + h * 64 + c * 4;
        CP16(sptr(&ds[r * QST2 + c * 4]), sr);
    }
    for (int e = tid; e < 2048; e += 256) {
        int arr = e >> 10, r = (e & 1023) >> 4, c = e & 15;
        uint32_t* ds = arr ? Kl : Kh;
        const uint32_t* sr = (arr ? g_kl : g_kh) + (size_t)(b * SEQ + r) * HW + h * 64 + c * 4;
        CP16(sptr(&ds[r * KST2 + c * 4]), sr);
    }
    size_t vtb = (size_t)((b * NH + h) * HD) * (SEQ / 2);
    for (int e = tid; e < 2048; e += 256) {
        int arr = e >> 10, r = (e & 1023) >> 3, c = e & 7;
        uint32_t* ds = Vst + arr * 4608;
        const uint32_t* sr = (arr ? g_vtl : g_vth) + vtb + (size_t)r * (SEQ / 2) + c * 4;
        CP16(sptr(&ds[r * VST2 + c * 4]), sr);
    }
    CPC;
    float o[16][4];
#pragma unroll
    for (int i = 0; i < 16; i++) { o[i][0] = o[i][1] = o[i][2] = o[i][3] = 0.f; }
    float m_lo = -1e30f, m_hi = -1e30f, l_lo = 0.f, l_hi = 0.f;
    int wr = w * 16;
    const int r_lo = wr + gr, r_hi = wr + gr + 8;
    for (int kt = 0; kt < SEQ / 64; kt++) {
        CPW(0);
        __syncthreads();
        float c[8][4];
#pragma unroll
        for (int j = 0; j < 8; j++) { c[j][0] = c[j][1] = c[j][2] = c[j][3] = 0.f; }
#pragma unroll
        for (int ks = 0; ks < 8; ks++) {
            int cb = ks * 8;
            uint32_t ah0 = Qh[r_lo * QST2 + cb + gc], ah1 = Qh[r_hi * QST2 + cb + gc];
            uint32_t ah2 = Qh[r_lo * QST2 + cb + gc + 4], ah3 = Qh[r_hi * QST2 + cb + gc + 4];
            uint32_t al0 = Ql[r_lo * QST2 + cb + gc], al1 = Ql[r_hi * QST2 + cb + gc];
            uint32_t al2 = Ql[r_lo * QST2 + cb + gc + 4], al3 = Ql[r_hi * QST2 + cb + gc + 4];
#pragma unroll
            for (int nb = 0; nb < 8; nb++) {
                uint32_t bh0 = Kh[(nb * 8 + gr) * KST2 + cb + gc];
                uint32_t bh1 = Kh[(nb * 8 + gr) * KST2 + cb + gc + 4];
                uint32_t bl0 = Kl[(nb * 8 + gr) * KST2 + cb + gc];
                uint32_t bl1 = Kl[(nb * 8 + gr) * KST2 + cb + gc + 4];
                MMAH(c[nb], ah0, ah1, ah2, ah3, bh0, bh1);
                MMAH(c[nb], ah0, ah1, ah2, ah3, bl0, bl1);
                MMAH(c[nb], al0, al1, al2, al3, bh0, bh1);
            }
        }
        // online softmax
        float mx_lo = -1e30f, mx_hi = -1e30f;
#pragma unroll
        for (int j = 0; j < 8; j++) {
            mx_lo = fmaxf(mx_lo, fmaxf(c[j][0], c[j][1]));
            mx_hi = fmaxf(mx_hi, fmaxf(c[j][2], c[j][3]));
        }
        mx_lo = fmaxf(mx_lo, __shfl_xor_sync(0xffffffffu, mx_lo, 1));
        mx_lo = fmaxf(mx_lo, __shfl_xor_sync(0xffffffffu, mx_lo, 2));
        mx_hi = fmaxf(mx_hi, __shfl_xor_sync(0xffffffffu, mx_hi, 1));
        mx_hi = fmaxf(mx_hi, __shfl_xor_sync(0xffffffffu, mx_hi, 2));
        float mn_lo = fmaxf(m_lo, mx_lo * scale);
        float mn_hi = fmaxf(m_hi, mx_hi * scale);
        float ts_lo = 0.f, ts_hi = 0.f;
#pragma unroll
        for (int j = 0; j < 8; j++) {
            c[j][0] = __expf(fmaf(c[j][0], scale, -mn_lo));
            c[j][1] = __expf(fmaf(c[j][1], scale, -mn_lo));
            c[j][2] = __expf(fmaf(c[j][2], scale, -mn_hi));
            c[j][3] = __expf(fmaf(c[j][3], scale, -mn_hi));
            ts_lo += c[j][0] + c[j][1];
            ts_hi += c[j][2] + c[j][3];
        }
        ts_lo += __shfl_xor_sync(0xffffffffu, ts_lo, 1);
        ts_lo += __shfl_xor_sync(0xffffffffu, ts_lo, 2);
        ts_hi += __shfl_xor_sync(0xffffffffu, ts_hi, 1);
        ts_hi += __shfl_xor_sync(0xffffffffu, ts_hi, 2);
        float co_lo = __expf(m_lo - mn_lo), co_hi = __expf(m_hi - mn_hi);
        m_lo = mn_lo; m_hi = mn_hi;
        l_lo = l_lo * co_lo + ts_lo;
        l_hi = l_hi * co_hi + ts_hi;
#pragma unroll
        for (int j = 0; j < 16; j++) {
            o[j][0] *= co_lo; o[j][1] *= co_lo;
            o[j][2] *= co_hi; o[j][3] *= co_hi;
        }
        // stash P (split)
#pragma unroll
        for (int j = 0; j < 8; j++) {
            uint32_t ph, pl;
            h2split(c[j][0], c[j][1], ph, pl);
            Ph[r_lo * PST2 + 4 * j + gc] = ph;
            Pl[r_lo * PST2 + 4 * j + gc] = pl;
            h2split(c[j][2], c[j][3], ph, pl);
            Ph[r_hi * PST2 + 4 * j + gc] = ph;
            Pl[r_hi * PST2 + 4 * j + gc] = pl;
        }
        __syncthreads();  // all warps done reading K; P visible
        // prefetch K(t+1) into Kbuf, V(t+1) into other V stage
        if (kt < SEQ / 64 - 1) {
            int nk = kt + 1;
            for (int e = tid; e < 2048; e += 256) {
                int arr = e >> 10, r = (e & 1023) >> 4, c2 = e & 15;
                uint32_t* ds = arr ? Kl : Kh;
                const uint32_t* sr = (arr ? g_kl : g_kh) + (size_t)(b * SEQ + nk * 64 + r) * HW + h * 64 + c2 * 4;
                CP16(sptr(&ds[r * KST2 + c2 * 4]), sr);
            }
            uint32_t* vdst = Vst + (nk & 1) * 9216;
            for (int e = tid; e < 2048; e += 256) {
                int arr = e >> 10, r = (e & 1023) >> 3, c2 = e & 7;
                uint32_t* ds = vdst + arr * 4608;
                const uint32_t* sr = (arr ? g_vtl : g_vth) + vtb + (size_t)r * (SEQ / 2) + nk * 32 + c2 * 4;
                CP16(sptr(&ds[r * VST2 + c2 * 4]), sr);
            }
            CPC;
        }
        // P @ V from current stage
        uint32_t* Vh = Vst + (kt & 1) * 9216;
        uint32_t* Vl = Vh + 4608;
#pragma unroll
        for (int ks = 0; ks < 4; ks++) {
            int cb = ks * 8;
            uint32_t ah0 = Ph[r_lo * PST2 + cb + gc], ah1 = Ph[r_hi * PST2 + cb + gc];
            uint32_t ah2 = Ph[r_lo * PST2 + cb + gc + 4], ah3 = Ph[r_hi * PST2 + cb + gc + 4];
            uint32_t al0 = Pl[r_lo * PST2 + cb + gc], al1 = Pl[r_hi * PST2 + cb + gc];
            uint32_t al2 = Pl[r_lo * PST2 + cb + gc + 4], al3 = Pl[r_hi * PST2 + cb + gc + 4];
#pragma unroll
            for (int nb = 0; nb < 16; nb++) {
                uint32_t bh0 = Vh[(nb * 8 + gr) * VST2 + cb + gc];
                uint32_t bh1 = Vh[(nb * 8 + gr) * VST2 + cb + gc + 4];
                uint32_t bl0 = Vl[(nb * 8 + gr) * VST2 + cb + gc];
                uint32_t bl1 = Vl[(nb * 8 + gr) * VST2 + cb + gc + 4];
                MMAH(o[nb], ah0, ah1, ah2, ah3, bh0, bh1);
                MMAH(o[nb], ah0, ah1, ah2, ah3, bl0, bl1);
                MMAH(o[nb], al0, al1, al2, al3, bh0, bh1);
            }
        }
    }
    float inv_lo = 1.f / l_lo, inv_hi = 1.f / l_hi;
    float* d_lo = g_ctx + ((size_t)(b * SEQ + q0 + r_lo)) * HID + h * HD;
    float* d_hi = g_ctx + ((size_t)(b * SEQ + q0 + r_hi)) * HID + h * HD;
#pragma unroll
    for (int nb = 0; nb < 16; nb++) {
        *(float2*)&d_lo[nb * 8 + 2 * gc] = make_float2(o[nb][0] * inv_lo, o[nb][1] * inv_lo);
        *(float2*)&d_hi[nb * 8 + 2 * gc] = make_float2(o[nb][2] * inv_hi, o[nb][3] * inv_hi);
    }
}

extern "C" void kernel_launch(void* const* d_in, const int* in_sizes, int n_in,
                              void* d_out, int out_size) {
    const float* x = (const float*)d_in[0];
    const float* wq = (const float*)d_in[1];
    const float* wk = (const float*)d_in[2];
    const float* wv = (const float*)d_in[3];
    const float* wo = (const float*)d_in[4];
    float* out = (float*)d_out;
    cudaFuncSetAttribute(k_attn, cudaFuncAttributeMaxDynamicSharedMemorySize, ATTN_SMEM);
    k_tab<<<256, 512>>>();
    k_wabs_partial<<<dim3(64, 4), 256>>>(wq, wk, wv, wo);
    k_wabs_final<<<4, 64>>>();
    k_quant_w<<<dim3(HID * HID / 1024, 4), 256>>>(wq, wk, wv, wo);
    k_quant_act<<<TOK, 256>>>(x, 0);
    k_gemm<<<dim3(16, 32), 256>>>(0, out);
    k_gemm<<<dim3(16, 32), 256>>>(1, out);
    k_gemm<<<dim3(16, 32), 256>>>(2, out);
    k_rope<<<TOK, 256>>>();
    k_vt<<<dim3(SEQ / 32, HD / 32, NH * 2), dim3(32, 8)>>>();
    k_attn<<<dim3(NH, 2, SEQ / 128), 256, ATTN_SMEM>>>();
    k_quant_act<<<TOK, 256>>>(nullptr, 1);
    k_gemm<<<dim3(16, 32), 256>>>(3, out);
}